// round 10
// baseline (speedup 1.0000x reference)
#include <cuda_runtime.h>
#include <cuda_fp16.h>
#include <math.h>

#define NN   99000
#define NH   64
#define NNZC 1584000
#define NADJ 6
#define NPT  33000
#define NT   97          // scan tiles per adjacency: ceil(99000/1024)

// ---------------- scratch (device globals; no runtime allocation) ----------------
__device__ __half g_st[2][3][NN * NH];   // fp16 states s0,s1,s2 per meta
__device__ float  g_t[2][NN * NH];       // gelu output per meta
__device__ float  g_logits[NN * 2];
__device__ float  g_Wc[2][3][NH * NH];   // composed weights, transposed: [k_in*64 + i_out]
__device__ float  g_bc[2][3][NH];        // composed biases
__device__ int    g_need[NADJ];          // adjacency used by any (meta,step)?

// CSR scratch
__device__ int  g_cursor[NADJ * NN];
__device__ int  g_rowptr[NADJ * (NN + 1)];
__device__ int  g_tilesum[NADJ * NT];
__device__ int  g_tileoff[NADJ * NT];
__device__ int2 g_pack[(size_t)NADJ * NNZC];  // (col, val bits) sorted by row

__device__ __forceinline__ const __half* st_ptr(int m, int id) {
    return g_st[m][id];
}

__device__ __forceinline__ float warp_sum(float v) {
    #pragma unroll
    for (int o = 16; o > 0; o >>= 1) v += __shfl_xor_sync(0xffffffffu, v, o);
    return v;
}

// ---------------- need flags ----------------
__global__ void need_kernel(const int* __restrict__ idxes_seq,
                            const int* __restrict__ idxes_res) {
    int a = threadIdx.x;
    if (a >= NADJ) return;
    int need = 0;
    for (int i = 0; i < 6; i++) {
        if (idxes_seq[i] == a) need = 1;
        if (idxes_res[i] == a) need = 1;
    }
    g_need[a] = need;
}

// ---------------- CSR build ----------------
__global__ void zero_counts_kernel() {
    int i = blockIdx.x * 256 + threadIdx.x;
    if (i >= NADJ * NN) return;
    g_cursor[i] = 0;
}

__global__ void hist_kernel(const int* __restrict__ rows) {
    int i = blockIdx.x * 256 + threadIdx.x;
    if (i >= NADJ * NNZC / 8) return;
    int a = (i * 8) / NNZC;
    if (!g_need[a]) return;
    int4 r0 = *(const int4*)&rows[i * 8];
    int4 r1 = *(const int4*)&rows[i * 8 + 4];
    int* cnt = g_cursor + a * NN;
    atomicAdd(&cnt[r0.x], 1); atomicAdd(&cnt[r0.y], 1);
    atomicAdd(&cnt[r0.z], 1); atomicAdd(&cnt[r0.w], 1);
    atomicAdd(&cnt[r1.x], 1); atomicAdd(&cnt[r1.y], 1);
    atomicAdd(&cnt[r1.z], 1); atomicAdd(&cnt[r1.w], 1);
}

__global__ void scanA_kernel() {
    __shared__ int sh[32];
    int a = blockIdx.y, tile = blockIdx.x;
    if (!g_need[a]) return;
    int idx = tile * 1024 + threadIdx.x;
    int lane = threadIdx.x & 31, wid = threadIdx.x >> 5;
    int v = (idx < NN) ? g_cursor[a * NN + idx] : 0;
    int s = v;
    #pragma unroll
    for (int o = 1; o < 32; o <<= 1) {
        int n = __shfl_up_sync(0xffffffffu, s, o);
        if (lane >= o) s += n;
    }
    if (lane == 31) sh[wid] = s;
    __syncthreads();
    if (wid == 0) {
        int w = sh[lane];
        #pragma unroll
        for (int o = 1; o < 32; o <<= 1) {
            int n = __shfl_up_sync(0xffffffffu, w, o);
            if (lane >= o) w += n;
        }
        sh[lane] = w;
    }
    __syncthreads();
    int incl = s + ((wid > 0) ? sh[wid - 1] : 0);
    if (idx < NN) g_rowptr[a * (NN + 1) + idx] = incl - v;
    if (threadIdx.x == 1023) g_tilesum[a * NT + tile] = incl;
}

__global__ void scanB_kernel() {
    __shared__ int sh[4];
    int a = blockIdx.x, t = threadIdx.x;
    if (!g_need[a]) return;
    int lane = t & 31, wid = t >> 5;
    int orig = (t < NT) ? g_tilesum[a * NT + t] : 0;
    int s = orig;
    #pragma unroll
    for (int o = 1; o < 32; o <<= 1) {
        int n = __shfl_up_sync(0xffffffffu, s, o);
        if (lane >= o) s += n;
    }
    if (lane == 31) sh[wid] = s;
    __syncthreads();
    int add = 0;
    for (int w = 0; w < wid; w++) add += sh[w];
    int incl = s + add;
    if (t < NT) g_tileoff[a * NT + t] = incl - orig;
    if (t == NT - 1) g_rowptr[a * (NN + 1) + NN] = incl;
}

__global__ void scanC_kernel() {
    int a = blockIdx.y;
    if (!g_need[a]) return;
    int idx = blockIdx.x * 1024 + threadIdx.x;
    if (idx >= NN) return;
    int off = g_tileoff[a * NT + blockIdx.x];
    int e = g_rowptr[a * (NN + 1) + idx] + off;
    g_rowptr[a * (NN + 1) + idx] = e;
    g_cursor[a * NN + idx] = e;
}

__global__ void scatter_kernel(const int* __restrict__ rows, const int* __restrict__ cols,
                               const float* __restrict__ vals) {
    int i = blockIdx.x * 256 + threadIdx.x;
    if (i >= NADJ * NNZC / 8) return;
    int a = (i * 8) / NNZC;
    if (!g_need[a]) return;
    int* cur = g_cursor + a * NN;
    int2* pk = (int2*)(g_pack + (size_t)a * NNZC);
    #pragma unroll
    for (int h = 0; h < 2; h++) {
        int base = i * 8 + h * 4;
        int4 r = *(const int4*)&rows[base];
        int4 c = *(const int4*)&cols[base];
        float4 v = *(const float4*)&vals[base];
        int p0 = atomicAdd(&cur[r.x], 1);
        int p1 = atomicAdd(&cur[r.y], 1);
        int p2 = atomicAdd(&cur[r.z], 1);
        int p3 = atomicAdd(&cur[r.w], 1);
        pk[p0] = make_int2(c.x, __float_as_int(v.x));
        pk[p1] = make_int2(c.y, __float_as_int(v.y));
        pk[p2] = make_int2(c.z, __float_as_int(v.z));
        pk[p3] = make_int2(c.w, __float_as_int(v.w));
    }
}

// ---------------- weight composition ----------------
__global__ void wcomb_kernel(const float* __restrict__ cW, const float* __restrict__ cb,
                             const float* __restrict__ wsW, const float* __restrict__ wsb) {
    __shared__ float cs[64][65];
    __shared__ float ws[64][65];
    int blk = blockIdx.x;
    int m = blk / 3;
    int t = blk % 3;
    int tid = threadIdx.x;
    for (int i = tid; i < 4096; i += 256) {
        int r = i >> 6, c = i & 63;
        cs[r][c] = cW[m * 4096 + i];
        ws[r][c] = wsW[t * 4096 + i];
    }
    __syncthreads();
    for (int e = tid; e < 4096; e += 256) {
        int i = e >> 6, k = e & 63;
        float acc = 0.f;
        #pragma unroll
        for (int q = 0; q < 64; q++) acc += cs[i][q] * ws[q][k];
        g_Wc[m][t][k * 64 + i] = acc;
    }
    if (tid < 64) {
        float acc = cb[m * 64 + tid];
        #pragma unroll
        for (int q = 0; q < 64; q++) acc += cs[tid][q] * wsb[t * 64 + q];
        g_bc[m][t][tid] = acc;
    }
}

// ---------------- fused s0: both metas from feats directly ----------------
__global__ void s0_kernel(const float* __restrict__ f0, const float* __restrict__ f1,
                          const float* __restrict__ f2) {
    __shared__ float Xs[64][68];
    __shared__ float Wt[64][64];
    __shared__ float bs[64];
    int type = blockIdx.y;
    const float* X = (type == 0) ? f0 : (type == 1) ? f1 : f2;
    int t = threadIdx.x;
    int lrow0 = blockIdx.x * 64;
    for (int i = t; i < 1024; i += 256) {
        int r = i >> 4, q = i & 15;
        float4 v = make_float4(0.f, 0.f, 0.f, 0.f);
        if (lrow0 + r < NPT) v = *(const float4*)&X[(size_t)(lrow0 + r) * 64 + q * 4];
        *(float4*)&Xs[r][q * 4] = v;
    }
    int nd = t >> 3;
    int cg = (t & 7) * 8;
    #pragma unroll
    for (int m = 0; m < 2; m++) {
        __syncthreads();
        for (int i = t; i < 4096; i += 256) ((float*)Wt)[i] = g_Wc[m][type][i];
        if (t < 64) bs[t] = g_bc[m][type][t];
        __syncthreads();
        float acc0[8], acc1[8];
        #pragma unroll
        for (int j = 0; j < 8; j++) { acc0[j] = bs[cg + j]; acc1[j] = bs[cg + j]; }
        #pragma unroll
        for (int k = 0; k < 64; k++) {
            float x0 = Xs[nd][k];
            float x1 = Xs[nd + 32][k];
            float4 w0 = *(const float4*)&Wt[k][cg];
            float4 w1 = *(const float4*)&Wt[k][cg + 4];
            acc0[0] += x0 * w0.x; acc0[1] += x0 * w0.y; acc0[2] += x0 * w0.z; acc0[3] += x0 * w0.w;
            acc0[4] += x0 * w1.x; acc0[5] += x0 * w1.y; acc0[6] += x0 * w1.z; acc0[7] += x0 * w1.w;
            acc1[0] += x1 * w0.x; acc1[1] += x1 * w0.y; acc1[2] += x1 * w0.z; acc1[3] += x1 * w0.w;
            acc1[4] += x1 * w1.x; acc1[5] += x1 * w1.y; acc1[6] += x1 * w1.z; acc1[7] += x1 * w1.w;
        }
        __half* D = (__half*)g_st[m][0];
        int r0 = type * NPT + lrow0 + nd;
        int r1 = r0 + 32;
        if (lrow0 + nd < NPT) {
            __half2* yp = (__half2*)&D[(size_t)r0 * 64 + cg];
            yp[0] = __floats2half2_rn(acc0[0], acc0[1]);
            yp[1] = __floats2half2_rn(acc0[2], acc0[3]);
            yp[2] = __floats2half2_rn(acc0[4], acc0[5]);
            yp[3] = __floats2half2_rn(acc0[6], acc0[7]);
        }
        if (lrow0 + nd + 32 < NPT) {
            __half2* yp = (__half2*)&D[(size_t)r1 * 64 + cg];
            yp[0] = __floats2half2_rn(acc1[0], acc1[1]);
            yp[1] = __floats2half2_rn(acc1[2], acc1[3]);
            yp[2] = __floats2half2_rn(acc1[4], acc1[5]);
            yp[3] = __floats2half2_rn(acc1[6], acc1[7]);
        }
    }
}

// ---------------- gather core (R8 form: int2 metadata, 8-edge batches) ----------------
__device__ __forceinline__ void gath_pass(const __half* __restrict__ S, int aidx,
                                          int row, int lane2, float& ax, float& ay) {
    const int* rp = g_rowptr + aidx * (NN + 1);
    int j   = rp[row];
    int end = rp[row + 1];
    const int2* __restrict__ pk = g_pack + (size_t)aidx * NNZC;

    for (; j + 8 <= end; j += 8) {
        int2 e0 = pk[j],     e1 = pk[j + 1], e2 = pk[j + 2], e3 = pk[j + 3];
        int2 e4 = pk[j + 4], e5 = pk[j + 5], e6 = pk[j + 6], e7 = pk[j + 7];
        float2 x0 = __half22float2(*(const __half2*)&S[(size_t)e0.x * 64 + lane2]);
        float2 x1 = __half22float2(*(const __half2*)&S[(size_t)e1.x * 64 + lane2]);
        float2 x2 = __half22float2(*(const __half2*)&S[(size_t)e2.x * 64 + lane2]);
        float2 x3 = __half22float2(*(const __half2*)&S[(size_t)e3.x * 64 + lane2]);
        float2 x4 = __half22float2(*(const __half2*)&S[(size_t)e4.x * 64 + lane2]);
        float2 x5 = __half22float2(*(const __half2*)&S[(size_t)e5.x * 64 + lane2]);
        float2 x6 = __half22float2(*(const __half2*)&S[(size_t)e6.x * 64 + lane2]);
        float2 x7 = __half22float2(*(const __half2*)&S[(size_t)e7.x * 64 + lane2]);
        ax += __int_as_float(e0.y) * x0.x; ay += __int_as_float(e0.y) * x0.y;
        ax += __int_as_float(e1.y) * x1.x; ay += __int_as_float(e1.y) * x1.y;
        ax += __int_as_float(e2.y) * x2.x; ay += __int_as_float(e2.y) * x2.y;
        ax += __int_as_float(e3.y) * x3.x; ay += __int_as_float(e3.y) * x3.y;
        ax += __int_as_float(e4.y) * x4.x; ay += __int_as_float(e4.y) * x4.y;
        ax += __int_as_float(e5.y) * x5.x; ay += __int_as_float(e5.y) * x5.y;
        ax += __int_as_float(e6.y) * x6.x; ay += __int_as_float(e6.y) * x6.y;
        ax += __int_as_float(e7.y) * x7.x; ay += __int_as_float(e7.y) * x7.y;
    }
    for (; j + 4 <= end; j += 4) {
        int2 e0 = pk[j], e1 = pk[j + 1], e2 = pk[j + 2], e3 = pk[j + 3];
        float2 x0 = __half22float2(*(const __half2*)&S[(size_t)e0.x * 64 + lane2]);
        float2 x1 = __half22float2(*(const __half2*)&S[(size_t)e1.x * 64 + lane2]);
        float2 x2 = __half22float2(*(const __half2*)&S[(size_t)e2.x * 64 + lane2]);
        float2 x3 = __half22float2(*(const __half2*)&S[(size_t)e3.x * 64 + lane2]);
        ax += __int_as_float(e0.y) * x0.x; ay += __int_as_float(e0.y) * x0.y;
        ax += __int_as_float(e1.y) * x1.x; ay += __int_as_float(e1.y) * x1.y;
        ax += __int_as_float(e2.y) * x2.x; ay += __int_as_float(e2.y) * x2.y;
        ax += __int_as_float(e3.y) * x3.x; ay += __int_as_float(e3.y) * x3.y;
    }
    for (; j < end; j++) {
        int2 e = pk[j];
        float v = __int_as_float(e.y);
        float2 xv = __half22float2(*(const __half2*)&S[(size_t)e.x * 64 + lane2]);
        ax += v * xv.x; ay += v * xv.y;
    }
}

// ---------------- gather SpMM steps 1 & 2 (fp16 out), grid.y = meta ----------------
template<int NP>
__global__ void spmm_gather_kernel(const int* __restrict__ idxes_seq,
                                   const int* __restrict__ idxes_res) {
    int m = blockIdx.y;
    int gid = blockIdx.x * 256 + threadIdx.x;
    int row = gid >> 5;
    if (row >= NN) return;
    int lane2 = (threadIdx.x & 31) * 2;
    const int* seq = idxes_seq + m * 3;
    const int* res = idxes_res + m * 3;

    float ax = 0.f, ay = 0.f;
    if (NP == 1) {
        gath_pass(st_ptr(m, 0), seq[0], row, lane2, ax, ay);
    } else {
        gath_pass(st_ptr(m, 1), seq[1], row, lane2, ax, ay);
        gath_pass(st_ptr(m, 0), res[0], row, lane2, ax, ay);
    }
    __half* D = (__half*)st_ptr(m, NP);
    *(__half2*)&D[(size_t)row * 64 + lane2] = __floats2half2_rn(ax, ay);
}

// ---------------- final gather + layernorm + gelu + attention logit, grid.y = meta ----------------
__global__ void spmm_final_kernel(const int* __restrict__ idxes_seq,
                                  const int* __restrict__ idxes_res,
                                  const float* __restrict__ norm_g,
                                  const float* __restrict__ norm_b,
                                  const float* __restrict__ A1, const float* __restrict__ b1,
                                  const float* __restrict__ a2, const float* __restrict__ b2) {
    __shared__ float A1s[64][68];
    __shared__ float hs[8][68];
    __shared__ float b1s[64];
    __shared__ float a2s[64];
    int m = blockIdx.y;
    int t = threadIdx.x;
    for (int i = t; i < 4096; i += 256) {
        int a = i >> 6, k = i & 63;
        A1s[a][k] = A1[i];
    }
    if (t < 64) { b1s[t] = b1[t]; a2s[t] = a2[t]; }
    __syncthreads();

    int w = t >> 5;
    int lane = t & 31;
    int lane2 = lane * 2;
    int row = blockIdx.x * 8 + w;
    if (row >= NN) return;
    const int* seq = idxes_seq + m * 3;
    const int* res = idxes_res + m * 3;

    float ax = 0.f, ay = 0.f;
    gath_pass(st_ptr(m, 2), seq[2], row, lane2, ax, ay);
    gath_pass(st_ptr(m, 0), res[1], row, lane2, ax, ay);
    gath_pass(st_ptr(m, 1), res[2], row, lane2, ax, ay);

    // layernorm (2 cols/lane) + exact gelu
    float mu = warp_sum(ax + ay) * (1.0f / 64.0f);
    float d0 = ax - mu, d1 = ay - mu;
    float var = warp_sum(d0 * d0 + d1 * d1) * (1.0f / 64.0f);
    float rstd = rsqrtf(var + 1e-5f);
    float2 gv = *(const float2*)&norm_g[m * 64 + lane2];
    float2 bv = *(const float2*)&norm_b[m * 64 + lane2];
    float n0 = d0 * rstd * gv.x + bv.x;
    float n1 = d1 * rstd * gv.y + bv.y;
    float ge0 = 0.5f * n0 * (1.0f + erff(n0 * 0.70710678118654752f));
    float ge1 = 0.5f * n1 * (1.0f + erff(n1 * 0.70710678118654752f));
    *(float2*)&g_t[m][(size_t)row * 64 + lane2] = make_float2(ge0, ge1);
    hs[w][lane2] = ge0;
    hs[w][lane2 + 1] = ge1;
    __syncwarp();

    // logit = tanh(A1 h + b1) . a2 + b2
    float part = 0.f;
    #pragma unroll
    for (int half = 0; half < 2; half++) {
        int a = lane + half * 32;
        float acc = b1s[a];
        #pragma unroll
        for (int k4 = 0; k4 < 16; k4++) {
            float4 wv = *(const float4*)&A1s[a][k4 * 4];
            float4 hv = *(const float4*)&hs[w][k4 * 4];
            acc += wv.x * hv.x + wv.y * hv.y + wv.z * hv.z + wv.w * hv.w;
        }
        part += tanhf(acc) * a2s[a];
    }
    part = warp_sum(part);
    if (lane == 0) g_logits[row * 2 + m] = part + b2[0];
}

// ---------------- 2-way softmax over metas + weighted sum -> out ----------------
__global__ void mix_kernel(float* __restrict__ out) {
    int idx = blockIdx.x * 256 + threadIdx.x;
    if (idx >= NN * 16) return;
    int node = idx >> 4, q = idx & 15;
    float l0 = g_logits[node * 2 + 0];
    float l1 = g_logits[node * 2 + 1];
    float mx = fmaxf(l0, l1);
    float e0 = expf(l0 - mx), e1 = expf(l1 - mx);
    float inv = 1.0f / (e0 + e1);
    float w0 = e0 * inv, w1 = e1 * inv;
    float4 a = *(const float4*)&g_t[0][(size_t)node * 64 + q * 4];
    float4 b = *(const float4*)&g_t[1][(size_t)node * 64 + q * 4];
    *(float4*)&out[(size_t)node * 64 + q * 4] =
        make_float4(w0 * a.x + w1 * b.x, w0 * a.y + w1 * b.y,
                    w0 * a.z + w1 * b.z, w0 * a.w + w1 * b.w);
}

extern "C" void kernel_launch(void* const* d_in, const int* in_sizes, int n_in,
                              void* d_out, int out_size) {
    const float* feats0      = (const float*)d_in[0];
    const float* feats1      = (const float*)d_in[1];
    const float* feats2      = (const float*)d_in[2];
    const float* ws_W        = (const float*)d_in[3];
    const float* ws_b        = (const float*)d_in[4];
    const float* adj_vals    = (const float*)d_in[5];
    const float* cell_aff_W  = (const float*)d_in[6];
    const float* cell_aff_b  = (const float*)d_in[7];
    const float* cell_norm_g = (const float*)d_in[8];
    const float* cell_norm_b = (const float*)d_in[9];
    const float* attn1_W     = (const float*)d_in[10];
    const float* attn1_b     = (const float*)d_in[11];
    const float* attn2_W     = (const float*)d_in[12];
    const float* attn2_b     = (const float*)d_in[13];
    // d_in[14] = node_types (contiguous blocks; unused)
    const int* adj_rows      = (const int*)d_in[15];
    const int* adj_cols      = (const int*)d_in[16];
    const int* idxes_seq     = (const int*)d_in[17];   // [2,3]
    const int* idxes_res     = (const int*)d_in[18];   // [2,3]
    float* out = (float*)d_out;

    const int S0_BLOCKS    = (NPT + 63) / 64;
    const int EDGE8_BLOCKS = (NADJ * NNZC / 8 + 255) / 256;
    const int CNT_BLOCKS   = (NADJ * NN + 255) / 256;
    const int GATH_BLOCKS  = (NN * 32 + 255) / 256;
    const int FIN_BLOCKS   = (NN + 7) / 8;
    const int MIX_BLOCKS   = (NN * 16 + 255) / 256;

    // ---- need flags + CSR build ----
    need_kernel<<<1, NADJ>>>(idxes_seq, idxes_res);
    zero_counts_kernel<<<CNT_BLOCKS, 256>>>();
    hist_kernel<<<EDGE8_BLOCKS, 256>>>(adj_rows);
    scanA_kernel<<<dim3(NT, NADJ), 1024>>>();
    scanB_kernel<<<NADJ, 128>>>();
    scanC_kernel<<<dim3(NT, NADJ), 1024>>>();
    scatter_kernel<<<EDGE8_BLOCKS, 256>>>(adj_rows, adj_cols, adj_vals);

    // ---- composed weights + fused s0 (both metas) ----
    wcomb_kernel<<<6, 256>>>(cell_aff_W, cell_aff_b, ws_W, ws_b);
    s0_kernel<<<dim3(S0_BLOCKS, 3), 256>>>(feats0, feats1, feats2);

    // ---- state chain, both metas per launch ----
    spmm_gather_kernel<1><<<dim3(GATH_BLOCKS, 2), 256>>>(idxes_seq, idxes_res);
    spmm_gather_kernel<2><<<dim3(GATH_BLOCKS, 2), 256>>>(idxes_seq, idxes_res);
    spmm_final_kernel<<<dim3(FIN_BLOCKS, 2), 256>>>(idxes_seq, idxes_res,
                                                    cell_norm_g, cell_norm_b,
                                                    attn1_W, attn1_b, attn2_W, attn2_b);

    mix_kernel<<<MIX_BLOCKS, 256>>>(out);
}

// round 11
// speedup vs baseline: 1.3086x; 1.3086x over previous
#include <cuda_runtime.h>
#include <cuda_fp16.h>
#include <math.h>

#define NN   99000
#define NH   64
#define NNZC 1584000
#define NADJ 6
#define NPT  33000
#define NT   97          // scan tiles per adjacency: ceil(99000/1024)

// ---------------- scratch (device globals; no runtime allocation) ----------------
__device__ __half g_st[2][3][NN * NH];   // fp16 states s0,s1,s2 per meta
__device__ float  g_s3[2][NN * NH];      // fp32 final state per meta
__device__ float  g_t[2][NN * NH];       // gelu output per meta
__device__ float  g_logits[NN * 2];
__device__ float  g_Wc[2][3][NH * NH];   // composed weights, transposed: [k_in*64 + i_out]
__device__ float  g_bc[2][3][NH];        // composed biases

// CSR scratch
__device__ int  g_cursor[NADJ * NN];
__device__ int  g_rowptr[NADJ * (NN + 1)];
__device__ int  g_tilesum[NADJ * NT];
__device__ int  g_tileoff[NADJ * NT];
__device__ int2 g_pack[(size_t)NADJ * NNZC];  // (col, val bits) sorted by row

__device__ __forceinline__ const __half* st_ptr(int m, int id) {
    return g_st[m][id];
}

__device__ __forceinline__ float warp_sum(float v) {
    #pragma unroll
    for (int o = 16; o > 0; o >>= 1) v += __shfl_xor_sync(0xffffffffu, v, o);
    return v;
}

// ---------------- CSR build ----------------
__global__ void zero_counts_kernel() {
    int i = blockIdx.x * 256 + threadIdx.x;
    if (i < NADJ * NN) g_cursor[i] = 0;
}

// 16 edges per thread (4x int4 loads) for atomic MLP
__global__ void hist_kernel(const int* __restrict__ rows) {
    int i = blockIdx.x * 256 + threadIdx.x;
    if (i >= NADJ * NNZC / 16) return;
    int a = (i * 16) / NNZC;          // NNZC % 16 == 0: all 16 edges same adjacency
    int* cnt = g_cursor + a * NN;
    #pragma unroll
    for (int h = 0; h < 4; h++) {
        int4 r = *(const int4*)&rows[i * 16 + h * 4];
        atomicAdd(&cnt[r.x], 1); atomicAdd(&cnt[r.y], 1);
        atomicAdd(&cnt[r.z], 1); atomicAdd(&cnt[r.w], 1);
    }
}

__global__ void scanA_kernel() {
    __shared__ int sh[32];
    int a = blockIdx.y, tile = blockIdx.x;
    int idx = tile * 1024 + threadIdx.x;
    int lane = threadIdx.x & 31, wid = threadIdx.x >> 5;
    int v = (idx < NN) ? g_cursor[a * NN + idx] : 0;
    int s = v;
    #pragma unroll
    for (int o = 1; o < 32; o <<= 1) {
        int n = __shfl_up_sync(0xffffffffu, s, o);
        if (lane >= o) s += n;
    }
    if (lane == 31) sh[wid] = s;
    __syncthreads();
    if (wid == 0) {
        int w = sh[lane];
        #pragma unroll
        for (int o = 1; o < 32; o <<= 1) {
            int n = __shfl_up_sync(0xffffffffu, w, o);
            if (lane >= o) w += n;
        }
        sh[lane] = w;
    }
    __syncthreads();
    int incl = s + ((wid > 0) ? sh[wid - 1] : 0);
    if (idx < NN) g_rowptr[a * (NN + 1) + idx] = incl - v;
    if (threadIdx.x == 1023) g_tilesum[a * NT + tile] = incl;
}

__global__ void scanB_kernel() {
    __shared__ int sh[4];
    int a = blockIdx.x, t = threadIdx.x;
    int lane = t & 31, wid = t >> 5;
    int orig = (t < NT) ? g_tilesum[a * NT + t] : 0;
    int s = orig;
    #pragma unroll
    for (int o = 1; o < 32; o <<= 1) {
        int n = __shfl_up_sync(0xffffffffu, s, o);
        if (lane >= o) s += n;
    }
    if (lane == 31) sh[wid] = s;
    __syncthreads();
    int add = 0;
    for (int w = 0; w < wid; w++) add += sh[w];
    int incl = s + add;
    if (t < NT) g_tileoff[a * NT + t] = incl - orig;
    if (t == NT - 1) g_rowptr[a * (NN + 1) + NN] = incl;
}

__global__ void scanC_kernel() {
    int a = blockIdx.y;
    int idx = blockIdx.x * 1024 + threadIdx.x;
    if (idx >= NN) return;
    int off = g_tileoff[a * NT + blockIdx.x];
    int e = g_rowptr[a * (NN + 1) + idx] + off;
    g_rowptr[a * (NN + 1) + idx] = e;
    g_cursor[a * NN + idx] = e;
}

// 16 edges per thread
__global__ void scatter_kernel(const int* __restrict__ rows, const int* __restrict__ cols,
                               const float* __restrict__ vals) {
    int i = blockIdx.x * 256 + threadIdx.x;
    if (i >= NADJ * NNZC / 16) return;
    int a = (i * 16) / NNZC;
    int* cur = g_cursor + a * NN;
    int2* pk = (int2*)(g_pack + (size_t)a * NNZC);
    #pragma unroll
    for (int h = 0; h < 4; h++) {
        int base = i * 16 + h * 4;
        int4 r = *(const int4*)&rows[base];
        int4 c = *(const int4*)&cols[base];
        float4 v = *(const float4*)&vals[base];
        int p0 = atomicAdd(&cur[r.x], 1);
        int p1 = atomicAdd(&cur[r.y], 1);
        int p2 = atomicAdd(&cur[r.z], 1);
        int p3 = atomicAdd(&cur[r.w], 1);
        pk[p0] = make_int2(c.x, __float_as_int(v.x));
        pk[p1] = make_int2(c.y, __float_as_int(v.y));
        pk[p2] = make_int2(c.z, __float_as_int(v.z));
        pk[p3] = make_int2(c.w, __float_as_int(v.w));
    }
}

// ---------------- weight composition ----------------
__global__ void wcomb_kernel(const float* __restrict__ cW, const float* __restrict__ cb,
                             const float* __restrict__ wsW, const float* __restrict__ wsb) {
    __shared__ float cs[64][65];
    __shared__ float ws[64][65];
    int blk = blockIdx.x;
    int m = blk / 3;
    int t = blk % 3;
    int tid = threadIdx.x;
    for (int i = tid; i < 4096; i += 256) {
        int r = i >> 6, c = i & 63;
        cs[r][c] = cW[m * 4096 + i];
        ws[r][c] = wsW[t * 4096 + i];
    }
    __syncthreads();
    for (int e = tid; e < 4096; e += 256) {
        int i = e >> 6, k = e & 63;
        float acc = 0.f;
        #pragma unroll
        for (int q = 0; q < 64; q++) acc += cs[i][q] * ws[q][k];
        g_Wc[m][t][k * 64 + i] = acc;
    }
    if (tid < 64) {
        float acc = cb[m * 64 + tid];
        #pragma unroll
        for (int q = 0; q < 64; q++) acc += cs[tid][q] * wsb[t * 64 + q];
        g_bc[m][t][tid] = acc;
    }
}

// ---------------- fused s0: both metas from feats directly ----------------
__global__ void s0_kernel(const float* __restrict__ f0, const float* __restrict__ f1,
                          const float* __restrict__ f2) {
    __shared__ float Xs[64][68];
    __shared__ float Wt[64][64];
    __shared__ float bs[64];
    int type = blockIdx.y;
    const float* X = (type == 0) ? f0 : (type == 1) ? f1 : f2;
    int t = threadIdx.x;
    int lrow0 = blockIdx.x * 64;
    for (int i = t; i < 1024; i += 256) {
        int r = i >> 4, q = i & 15;
        float4 v = make_float4(0.f, 0.f, 0.f, 0.f);
        if (lrow0 + r < NPT) v = *(const float4*)&X[(size_t)(lrow0 + r) * 64 + q * 4];
        *(float4*)&Xs[r][q * 4] = v;
    }
    int nd = t >> 3;
    int cg = (t & 7) * 8;
    #pragma unroll
    for (int m = 0; m < 2; m++) {
        __syncthreads();
        for (int i = t; i < 4096; i += 256) ((float*)Wt)[i] = g_Wc[m][type][i];
        if (t < 64) bs[t] = g_bc[m][type][t];
        __syncthreads();
        float acc0[8], acc1[8];
        #pragma unroll
        for (int j = 0; j < 8; j++) { acc0[j] = bs[cg + j]; acc1[j] = bs[cg + j]; }
        #pragma unroll
        for (int k = 0; k < 64; k++) {
            float x0 = Xs[nd][k];
            float x1 = Xs[nd + 32][k];
            float4 w0 = *(const float4*)&Wt[k][cg];
            float4 w1 = *(const float4*)&Wt[k][cg + 4];
            acc0[0] += x0 * w0.x; acc0[1] += x0 * w0.y; acc0[2] += x0 * w0.z; acc0[3] += x0 * w0.w;
            acc0[4] += x0 * w1.x; acc0[5] += x0 * w1.y; acc0[6] += x0 * w1.z; acc0[7] += x0 * w1.w;
            acc1[0] += x1 * w0.x; acc1[1] += x1 * w0.y; acc1[2] += x1 * w0.z; acc1[3] += x1 * w0.w;
            acc1[4] += x1 * w1.x; acc1[5] += x1 * w1.y; acc1[6] += x1 * w1.z; acc1[7] += x1 * w1.w;
        }
        __half* D = (__half*)g_st[m][0];
        int r0 = type * NPT + lrow0 + nd;
        int r1 = r0 + 32;
        if (lrow0 + nd < NPT) {
            __half2* yp = (__half2*)&D[(size_t)r0 * 64 + cg];
            yp[0] = __floats2half2_rn(acc0[0], acc0[1]);
            yp[1] = __floats2half2_rn(acc0[2], acc0[3]);
            yp[2] = __floats2half2_rn(acc0[4], acc0[5]);
            yp[3] = __floats2half2_rn(acc0[6], acc0[7]);
        }
        if (lrow0 + nd + 32 < NPT) {
            __half2* yp = (__half2*)&D[(size_t)r1 * 64 + cg];
            yp[0] = __floats2half2_rn(acc1[0], acc1[1]);
            yp[1] = __floats2half2_rn(acc1[2], acc1[3]);
            yp[2] = __floats2half2_rn(acc1[4], acc1[5]);
            yp[3] = __floats2half2_rn(acc1[6], acc1[7]);
        }
    }
}

// ---------------- gather core (int2 metadata, 8-edge batches) ----------------
__device__ __forceinline__ void gath_pass(const __half* __restrict__ S, int aidx,
                                          int row, int lane2, float& ax, float& ay) {
    const int* rp = g_rowptr + aidx * (NN + 1);
    int j   = rp[row];
    int end = rp[row + 1];
    const int2* __restrict__ pk = g_pack + (size_t)aidx * NNZC;

    for (; j + 8 <= end; j += 8) {
        int2 e0 = pk[j],     e1 = pk[j + 1], e2 = pk[j + 2], e3 = pk[j + 3];
        int2 e4 = pk[j + 4], e5 = pk[j + 5], e6 = pk[j + 6], e7 = pk[j + 7];
        float2 x0 = __half22float2(*(const __half2*)&S[(size_t)e0.x * 64 + lane2]);
        float2 x1 = __half22float2(*(const __half2*)&S[(size_t)e1.x * 64 + lane2]);
        float2 x2 = __half22float2(*(const __half2*)&S[(size_t)e2.x * 64 + lane2]);
        float2 x3 = __half22float2(*(const __half2*)&S[(size_t)e3.x * 64 + lane2]);
        float2 x4 = __half22float2(*(const __half2*)&S[(size_t)e4.x * 64 + lane2]);
        float2 x5 = __half22float2(*(const __half2*)&S[(size_t)e5.x * 64 + lane2]);
        float2 x6 = __half22float2(*(const __half2*)&S[(size_t)e6.x * 64 + lane2]);
        float2 x7 = __half22float2(*(const __half2*)&S[(size_t)e7.x * 64 + lane2]);
        ax += __int_as_float(e0.y) * x0.x; ay += __int_as_float(e0.y) * x0.y;
        ax += __int_as_float(e1.y) * x1.x; ay += __int_as_float(e1.y) * x1.y;
        ax += __int_as_float(e2.y) * x2.x; ay += __int_as_float(e2.y) * x2.y;
        ax += __int_as_float(e3.y) * x3.x; ay += __int_as_float(e3.y) * x3.y;
        ax += __int_as_float(e4.y) * x4.x; ay += __int_as_float(e4.y) * x4.y;
        ax += __int_as_float(e5.y) * x5.x; ay += __int_as_float(e5.y) * x5.y;
        ax += __int_as_float(e6.y) * x6.x; ay += __int_as_float(e6.y) * x6.y;
        ax += __int_as_float(e7.y) * x7.x; ay += __int_as_float(e7.y) * x7.y;
    }
    for (; j + 4 <= end; j += 4) {
        int2 e0 = pk[j], e1 = pk[j + 1], e2 = pk[j + 2], e3 = pk[j + 3];
        float2 x0 = __half22float2(*(const __half2*)&S[(size_t)e0.x * 64 + lane2]);
        float2 x1 = __half22float2(*(const __half2*)&S[(size_t)e1.x * 64 + lane2]);
        float2 x2 = __half22float2(*(const __half2*)&S[(size_t)e2.x * 64 + lane2]);
        float2 x3 = __half22float2(*(const __half2*)&S[(size_t)e3.x * 64 + lane2]);
        ax += __int_as_float(e0.y) * x0.x; ay += __int_as_float(e0.y) * x0.y;
        ax += __int_as_float(e1.y) * x1.x; ay += __int_as_float(e1.y) * x1.y;
        ax += __int_as_float(e2.y) * x2.x; ay += __int_as_float(e2.y) * x2.y;
        ax += __int_as_float(e3.y) * x3.x; ay += __int_as_float(e3.y) * x3.y;
    }
    for (; j < end; j++) {
        int2 e = pk[j];
        float v = __int_as_float(e.y);
        float2 xv = __half22float2(*(const __half2*)&S[(size_t)e.x * 64 + lane2]);
        ax += v * xv.x; ay += v * xv.y;
    }
}

// ---------------- gather SpMM steps (fp16 out for NP=1,2; fp32 s3 for NP=3), grid.y = meta ----------------
template<int NP>
__global__ void spmm_gather_kernel(const int* __restrict__ idxes_seq,
                                   const int* __restrict__ idxes_res) {
    int m = blockIdx.y;
    int gid = blockIdx.x * 256 + threadIdx.x;
    int row = gid >> 5;
    if (row >= NN) return;
    int lane2 = (threadIdx.x & 31) * 2;
    const int* seq = idxes_seq + m * 3;
    const int* res = idxes_res + m * 3;

    float ax = 0.f, ay = 0.f;
    if (NP == 1) {
        gath_pass(st_ptr(m, 0), seq[0], row, lane2, ax, ay);
    } else if (NP == 2) {
        gath_pass(st_ptr(m, 1), seq[1], row, lane2, ax, ay);
        gath_pass(st_ptr(m, 0), res[0], row, lane2, ax, ay);
    } else {
        gath_pass(st_ptr(m, 2), seq[2], row, lane2, ax, ay);
        gath_pass(st_ptr(m, 0), res[1], row, lane2, ax, ay);
        gath_pass(st_ptr(m, 1), res[2], row, lane2, ax, ay);
    }
    if (NP == 3) {
        *(float2*)&g_s3[m][(size_t)row * 64 + lane2] = make_float2(ax, ay);
    } else {
        __half* D = (__half*)st_ptr(m, NP);
        *(__half2*)&D[(size_t)row * 64 + lane2] = __floats2half2_rn(ax, ay);
    }
}

// ---------------- layernorm + exact gelu + attention logit; grid.y = meta ----------------
__global__ void post_kernel(const float* __restrict__ norm_g, const float* __restrict__ norm_b,
                            const float* __restrict__ A1, const float* __restrict__ b1,
                            const float* __restrict__ a2, const float* __restrict__ b2) {
    __shared__ float A1s[64][68];
    __shared__ float hs[8][68];
    __shared__ float b1s[64];
    __shared__ float a2s[64];
    int meta = blockIdx.y;
    const float* gvec = norm_g + meta * 64;
    const float* bvec = norm_b + meta * 64;
    int t = threadIdx.x;
    for (int i = t; i < 4096; i += 256) {
        int a = i >> 6, k = i & 63;
        A1s[a][k] = A1[i];
    }
    if (t < 64) { b1s[t] = b1[t]; a2s[t] = a2[t]; }
    __syncthreads();

    int w = t >> 5;
    int lane = t & 31;
    int node = blockIdx.x * 8 + w;
    if (node >= NN) return;

    float* T = g_t[meta];
    const float* S = g_s3[meta];

    float h0 = S[(size_t)node * 64 + lane];
    float h1 = S[(size_t)node * 64 + lane + 32];
    float mu = warp_sum(h0 + h1) * (1.0f / 64.0f);
    float d0 = h0 - mu, d1 = h1 - mu;
    float var = warp_sum(d0 * d0 + d1 * d1) * (1.0f / 64.0f);
    float rstd = rsqrtf(var + 1e-5f);
    float n0 = d0 * rstd * gvec[lane] + bvec[lane];
    float n1 = d1 * rstd * gvec[lane + 32] + bvec[lane + 32];
    float ge0 = 0.5f * n0 * (1.0f + erff(n0 * 0.70710678118654752f));
    float ge1 = 0.5f * n1 * (1.0f + erff(n1 * 0.70710678118654752f));
    T[(size_t)node * 64 + lane] = ge0;
    T[(size_t)node * 64 + lane + 32] = ge1;
    hs[w][lane] = ge0;
    hs[w][lane + 32] = ge1;
    __syncwarp();

    float part = 0.f;
    #pragma unroll
    for (int half = 0; half < 2; half++) {
        int a = lane + half * 32;
        float acc = b1s[a];
        #pragma unroll
        for (int k4 = 0; k4 < 16; k4++) {
            float4 wv = *(const float4*)&A1s[a][k4 * 4];
            float4 hv = *(const float4*)&hs[w][k4 * 4];
            acc += wv.x * hv.x + wv.y * hv.y + wv.z * hv.z + wv.w * hv.w;
        }
        part += tanhf(acc) * a2s[a];
    }
    part = warp_sum(part);
    if (lane == 0) g_logits[node * 2 + meta] = part + b2[0];
}

// ---------------- 2-way softmax over metas + weighted sum -> out ----------------
__global__ void mix_kernel(float* __restrict__ out) {
    int idx = blockIdx.x * 256 + threadIdx.x;
    if (idx >= NN * 16) return;
    int node = idx >> 4, q = idx & 15;
    float l0 = g_logits[node * 2 + 0];
    float l1 = g_logits[node * 2 + 1];
    float mx = fmaxf(l0, l1);
    float e0 = expf(l0 - mx), e1 = expf(l1 - mx);
    float inv = 1.0f / (e0 + e1);
    float w0 = e0 * inv, w1 = e1 * inv;
    float4 a = *(const float4*)&g_t[0][(size_t)node * 64 + q * 4];
    float4 b = *(const float4*)&g_t[1][(size_t)node * 64 + q * 4];
    *(float4*)&out[(size_t)node * 64 + q * 4] =
        make_float4(w0 * a.x + w1 * b.x, w0 * a.y + w1 * b.y,
                    w0 * a.z + w1 * b.z, w0 * a.w + w1 * b.w);
}

extern "C" void kernel_launch(void* const* d_in, const int* in_sizes, int n_in,
                              void* d_out, int out_size) {
    const float* feats0      = (const float*)d_in[0];
    const float* feats1      = (const float*)d_in[1];
    const float* feats2      = (const float*)d_in[2];
    const float* ws_W        = (const float*)d_in[3];
    const float* ws_b        = (const float*)d_in[4];
    const float* adj_vals    = (const float*)d_in[5];
    const float* cell_aff_W  = (const float*)d_in[6];
    const float* cell_aff_b  = (const float*)d_in[7];
    const float* cell_norm_g = (const float*)d_in[8];
    const float* cell_norm_b = (const float*)d_in[9];
    const float* attn1_W     = (const float*)d_in[10];
    const float* attn1_b     = (const float*)d_in[11];
    const float* attn2_W     = (const float*)d_in[12];
    const float* attn2_b     = (const float*)d_in[13];
    // d_in[14] = node_types (contiguous blocks; unused)
    const int* adj_rows      = (const int*)d_in[15];
    const int* adj_cols      = (const int*)d_in[16];
    const int* idxes_seq     = (const int*)d_in[17];   // [2,3]
    const int* idxes_res     = (const int*)d_in[18];   // [2,3]
    float* out = (float*)d_out;

    const int S0_BLOCKS     = (NPT + 63) / 64;
    const int EDGE16_BLOCKS = (NADJ * NNZC / 16 + 255) / 256;
    const int CNT_BLOCKS    = (NADJ * NN + 255) / 256;
    const int GATH_BLOCKS   = (NN * 32 + 255) / 256;
    const int POST_BLOCKS   = (NN + 7) / 8;
    const int MIX_BLOCKS    = (NN * 16 + 255) / 256;

    // ---- CSR build ----
    zero_counts_kernel<<<CNT_BLOCKS, 256>>>();
    hist_kernel<<<EDGE16_BLOCKS, 256>>>(adj_rows);
    scanA_kernel<<<dim3(NT, NADJ), 1024>>>();
    scanB_kernel<<<NADJ, 128>>>();
    scanC_kernel<<<dim3(NT, NADJ), 1024>>>();
    scatter_kernel<<<EDGE16_BLOCKS, 256>>>(adj_rows, adj_cols, adj_vals);

    // ---- composed weights + fused s0 (both metas) ----
    wcomb_kernel<<<6, 256>>>(cell_aff_W, cell_aff_b, ws_W, ws_b);
    s0_kernel<<<dim3(S0_BLOCKS, 3), 256>>>(feats0, feats1, feats2);

    // ---- state chain, both metas per launch ----
    spmm_gather_kernel<1><<<dim3(GATH_BLOCKS, 2), 256>>>(idxes_seq, idxes_res);
    spmm_gather_kernel<2><<<dim3(GATH_BLOCKS, 2), 256>>>(idxes_seq, idxes_res);
    spmm_gather_kernel<3><<<dim3(GATH_BLOCKS, 2), 256>>>(idxes_seq, idxes_res);

    // ---- post (both metas) + mix ----
    post_kernel<<<dim3(POST_BLOCKS, 2), 256>>>(cell_norm_g, cell_norm_b,
                                               attn1_W, attn1_b, attn2_W, attn2_b);
    mix_kernel<<<MIX_BLOCKS, 256>>>(out);
}

// round 12
// speedup vs baseline: 1.3382x; 1.0226x over previous
#include <cuda_runtime.h>
#include <cuda_fp16.h>
#include <math.h>

#define NN   99000
#define NH   64
#define NNZC 1584000
#define NADJ 6
#define NPT  33000
#define NT   97          // scan tiles per adjacency: ceil(99000/1024)

// ---------------- scratch (device globals; no runtime allocation) ----------------
__device__ __half g_st[2][3][NN * NH];   // fp16 states s0,s1,s2 per meta
__device__ float  g_s3[2][NN * NH];      // fp32 final state per meta
__device__ float  g_t[2][NN * NH];       // gelu output per meta
__device__ float  g_logits[NN * 2];
__device__ float  g_Wc[2][3][NH * NH];   // composed weights, transposed: [k_in*64 + i_out]
__device__ float  g_bc[2][3][NH];        // composed biases

// CSR scratch
__device__ int  g_cursor[NADJ * NN];
__device__ int  g_rowptr[NADJ * (NN + 1)];
__device__ int  g_tilesum[NADJ * NT];
__device__ int  g_tileoff[NADJ * NT];
__device__ int2 g_pack[(size_t)NADJ * NNZC];  // (col, val bits) sorted by row

__device__ __forceinline__ const __half* st_ptr(int m, int id) {
    return g_st[m][id];
}

__device__ __forceinline__ float warp_sum(float v) {
    #pragma unroll
    for (int o = 16; o > 0; o >>= 1) v += __shfl_xor_sync(0xffffffffu, v, o);
    return v;
}

// ---------------- CSR build ----------------
__global__ void zero_counts_kernel() {
    int i = blockIdx.x * 256 + threadIdx.x;
    if (i < NADJ * NN) g_cursor[i] = 0;
}

// 16 edges per thread (4x int4 loads) for atomic MLP
__global__ void hist_kernel(const int* __restrict__ rows) {
    int i = blockIdx.x * 256 + threadIdx.x;
    if (i >= NADJ * NNZC / 16) return;
    int a = (i * 16) / NNZC;          // NNZC % 16 == 0: all 16 edges same adjacency
    int* cnt = g_cursor + a * NN;
    #pragma unroll
    for (int h = 0; h < 4; h++) {
        int4 r = *(const int4*)&rows[i * 16 + h * 4];
        atomicAdd(&cnt[r.x], 1); atomicAdd(&cnt[r.y], 1);
        atomicAdd(&cnt[r.z], 1); atomicAdd(&cnt[r.w], 1);
    }
}

__global__ void scanA_kernel() {
    __shared__ int sh[32];
    int a = blockIdx.y, tile = blockIdx.x;
    int idx = tile * 1024 + threadIdx.x;
    int lane = threadIdx.x & 31, wid = threadIdx.x >> 5;
    int v = (idx < NN) ? g_cursor[a * NN + idx] : 0;
    int s = v;
    #pragma unroll
    for (int o = 1; o < 32; o <<= 1) {
        int n = __shfl_up_sync(0xffffffffu, s, o);
        if (lane >= o) s += n;
    }
    if (lane == 31) sh[wid] = s;
    __syncthreads();
    if (wid == 0) {
        int w = sh[lane];
        #pragma unroll
        for (int o = 1; o < 32; o <<= 1) {
            int n = __shfl_up_sync(0xffffffffu, w, o);
            if (lane >= o) w += n;
        }
        sh[lane] = w;
    }
    __syncthreads();
    int incl = s + ((wid > 0) ? sh[wid - 1] : 0);
    if (idx < NN) g_rowptr[a * (NN + 1) + idx] = incl - v;
    if (threadIdx.x == 1023) g_tilesum[a * NT + tile] = incl;
}

__global__ void scanB_kernel() {
    __shared__ int sh[4];
    int a = blockIdx.x, t = threadIdx.x;
    int lane = t & 31, wid = t >> 5;
    int orig = (t < NT) ? g_tilesum[a * NT + t] : 0;
    int s = orig;
    #pragma unroll
    for (int o = 1; o < 32; o <<= 1) {
        int n = __shfl_up_sync(0xffffffffu, s, o);
        if (lane >= o) s += n;
    }
    if (lane == 31) sh[wid] = s;
    __syncthreads();
    int add = 0;
    for (int w = 0; w < wid; w++) add += sh[w];
    int incl = s + add;
    if (t < NT) g_tileoff[a * NT + t] = incl - orig;
    if (t == NT - 1) g_rowptr[a * (NN + 1) + NN] = incl;
}

__global__ void scanC_kernel() {
    int a = blockIdx.y;
    int idx = blockIdx.x * 1024 + threadIdx.x;
    if (idx >= NN) return;
    int off = g_tileoff[a * NT + blockIdx.x];
    int e = g_rowptr[a * (NN + 1) + idx] + off;
    g_rowptr[a * (NN + 1) + idx] = e;
    g_cursor[a * NN + idx] = e;
}

// 16 edges per thread
__global__ void scatter_kernel(const int* __restrict__ rows, const int* __restrict__ cols,
                               const float* __restrict__ vals) {
    int i = blockIdx.x * 256 + threadIdx.x;
    if (i >= NADJ * NNZC / 16) return;
    int a = (i * 16) / NNZC;
    int* cur = g_cursor + a * NN;
    int2* pk = (int2*)(g_pack + (size_t)a * NNZC);
    #pragma unroll
    for (int h = 0; h < 4; h++) {
        int base = i * 16 + h * 4;
        int4 r = *(const int4*)&rows[base];
        int4 c = *(const int4*)&cols[base];
        float4 v = *(const float4*)&vals[base];
        int p0 = atomicAdd(&cur[r.x], 1);
        int p1 = atomicAdd(&cur[r.y], 1);
        int p2 = atomicAdd(&cur[r.z], 1);
        int p3 = atomicAdd(&cur[r.w], 1);
        pk[p0] = make_int2(c.x, __float_as_int(v.x));
        pk[p1] = make_int2(c.y, __float_as_int(v.y));
        pk[p2] = make_int2(c.z, __float_as_int(v.z));
        pk[p3] = make_int2(c.w, __float_as_int(v.w));
    }
}

// ---------------- weight composition ----------------
__global__ void wcomb_kernel(const float* __restrict__ cW, const float* __restrict__ cb,
                             const float* __restrict__ wsW, const float* __restrict__ wsb) {
    __shared__ float cs[64][65];
    __shared__ float ws[64][65];
    int blk = blockIdx.x;
    int m = blk / 3;
    int t = blk % 3;
    int tid = threadIdx.x;
    for (int i = tid; i < 4096; i += 256) {
        int r = i >> 6, c = i & 63;
        cs[r][c] = cW[m * 4096 + i];
        ws[r][c] = wsW[t * 4096 + i];
    }
    __syncthreads();
    for (int e = tid; e < 4096; e += 256) {
        int i = e >> 6, k = e & 63;
        float acc = 0.f;
        #pragma unroll
        for (int q = 0; q < 64; q++) acc += cs[i][q] * ws[q][k];
        g_Wc[m][t][k * 64 + i] = acc;
    }
    if (tid < 64) {
        float acc = cb[m * 64 + tid];
        #pragma unroll
        for (int q = 0; q < 64; q++) acc += cs[tid][q] * wsb[t * 64 + q];
        g_bc[m][t][tid] = acc;
    }
}

// ---------------- fused s0: both metas from feats directly ----------------
__global__ void s0_kernel(const float* __restrict__ f0, const float* __restrict__ f1,
                          const float* __restrict__ f2) {
    __shared__ float Xs[64][68];
    __shared__ float Wt[64][64];
    __shared__ float bs[64];
    int type = blockIdx.y;
    const float* X = (type == 0) ? f0 : (type == 1) ? f1 : f2;
    int t = threadIdx.x;
    int lrow0 = blockIdx.x * 64;
    for (int i = t; i < 1024; i += 256) {
        int r = i >> 4, q = i & 15;
        float4 v = make_float4(0.f, 0.f, 0.f, 0.f);
        if (lrow0 + r < NPT) v = *(const float4*)&X[(size_t)(lrow0 + r) * 64 + q * 4];
        *(float4*)&Xs[r][q * 4] = v;
    }
    int nd = t >> 3;
    int cg = (t & 7) * 8;
    #pragma unroll
    for (int m = 0; m < 2; m++) {
        __syncthreads();
        for (int i = t; i < 4096; i += 256) ((float*)Wt)[i] = g_Wc[m][type][i];
        if (t < 64) bs[t] = g_bc[m][type][t];
        __syncthreads();
        float acc0[8], acc1[8];
        #pragma unroll
        for (int j = 0; j < 8; j++) { acc0[j] = bs[cg + j]; acc1[j] = bs[cg + j]; }
        #pragma unroll
        for (int k = 0; k < 64; k++) {
            float x0 = Xs[nd][k];
            float x1 = Xs[nd + 32][k];
            float4 w0 = *(const float4*)&Wt[k][cg];
            float4 w1 = *(const float4*)&Wt[k][cg + 4];
            acc0[0] += x0 * w0.x; acc0[1] += x0 * w0.y; acc0[2] += x0 * w0.z; acc0[3] += x0 * w0.w;
            acc0[4] += x0 * w1.x; acc0[5] += x0 * w1.y; acc0[6] += x0 * w1.z; acc0[7] += x0 * w1.w;
            acc1[0] += x1 * w0.x; acc1[1] += x1 * w0.y; acc1[2] += x1 * w0.z; acc1[3] += x1 * w0.w;
            acc1[4] += x1 * w1.x; acc1[5] += x1 * w1.y; acc1[6] += x1 * w1.z; acc1[7] += x1 * w1.w;
        }
        __half* D = (__half*)g_st[m][0];
        int r0 = type * NPT + lrow0 + nd;
        int r1 = r0 + 32;
        if (lrow0 + nd < NPT) {
            __half2* yp = (__half2*)&D[(size_t)r0 * 64 + cg];
            yp[0] = __floats2half2_rn(acc0[0], acc0[1]);
            yp[1] = __floats2half2_rn(acc0[2], acc0[3]);
            yp[2] = __floats2half2_rn(acc0[4], acc0[5]);
            yp[3] = __floats2half2_rn(acc0[6], acc0[7]);
        }
        if (lrow0 + nd + 32 < NPT) {
            __half2* yp = (__half2*)&D[(size_t)r1 * 64 + cg];
            yp[0] = __floats2half2_rn(acc1[0], acc1[1]);
            yp[1] = __floats2half2_rn(acc1[2], acc1[3]);
            yp[2] = __floats2half2_rn(acc1[4], acc1[5]);
            yp[3] = __floats2half2_rn(acc1[6], acc1[7]);
        }
    }
}

// ---------------- gather core (int2 metadata, 8-edge batches) ----------------
__device__ __forceinline__ void gath_pass(const __half* __restrict__ S, int aidx,
                                          int row, int lane2, float& ax, float& ay) {
    const int* rp = g_rowptr + aidx * (NN + 1);
    int j   = rp[row];
    int end = rp[row + 1];
    const int2* __restrict__ pk = g_pack + (size_t)aidx * NNZC;

    for (; j + 8 <= end; j += 8) {
        int2 e0 = pk[j],     e1 = pk[j + 1], e2 = pk[j + 2], e3 = pk[j + 3];
        int2 e4 = pk[j + 4], e5 = pk[j + 5], e6 = pk[j + 6], e7 = pk[j + 7];
        float2 x0 = __half22float2(*(const __half2*)&S[(size_t)e0.x * 64 + lane2]);
        float2 x1 = __half22float2(*(const __half2*)&S[(size_t)e1.x * 64 + lane2]);
        float2 x2 = __half22float2(*(const __half2*)&S[(size_t)e2.x * 64 + lane2]);
        float2 x3 = __half22float2(*(const __half2*)&S[(size_t)e3.x * 64 + lane2]);
        float2 x4 = __half22float2(*(const __half2*)&S[(size_t)e4.x * 64 + lane2]);
        float2 x5 = __half22float2(*(const __half2*)&S[(size_t)e5.x * 64 + lane2]);
        float2 x6 = __half22float2(*(const __half2*)&S[(size_t)e6.x * 64 + lane2]);
        float2 x7 = __half22float2(*(const __half2*)&S[(size_t)e7.x * 64 + lane2]);
        ax += __int_as_float(e0.y) * x0.x; ay += __int_as_float(e0.y) * x0.y;
        ax += __int_as_float(e1.y) * x1.x; ay += __int_as_float(e1.y) * x1.y;
        ax += __int_as_float(e2.y) * x2.x; ay += __int_as_float(e2.y) * x2.y;
        ax += __int_as_float(e3.y) * x3.x; ay += __int_as_float(e3.y) * x3.y;
        ax += __int_as_float(e4.y) * x4.x; ay += __int_as_float(e4.y) * x4.y;
        ax += __int_as_float(e5.y) * x5.x; ay += __int_as_float(e5.y) * x5.y;
        ax += __int_as_float(e6.y) * x6.x; ay += __int_as_float(e6.y) * x6.y;
        ax += __int_as_float(e7.y) * x7.x; ay += __int_as_float(e7.y) * x7.y;
    }
    for (; j + 4 <= end; j += 4) {
        int2 e0 = pk[j], e1 = pk[j + 1], e2 = pk[j + 2], e3 = pk[j + 3];
        float2 x0 = __half22float2(*(const __half2*)&S[(size_t)e0.x * 64 + lane2]);
        float2 x1 = __half22float2(*(const __half2*)&S[(size_t)e1.x * 64 + lane2]);
        float2 x2 = __half22float2(*(const __half2*)&S[(size_t)e2.x * 64 + lane2]);
        float2 x3 = __half22float2(*(const __half2*)&S[(size_t)e3.x * 64 + lane2]);
        ax += __int_as_float(e0.y) * x0.x; ay += __int_as_float(e0.y) * x0.y;
        ax += __int_as_float(e1.y) * x1.x; ay += __int_as_float(e1.y) * x1.y;
        ax += __int_as_float(e2.y) * x2.x; ay += __int_as_float(e2.y) * x2.y;
        ax += __int_as_float(e3.y) * x3.x; ay += __int_as_float(e3.y) * x3.y;
    }
    for (; j < end; j++) {
        int2 e = pk[j];
        float v = __int_as_float(e.y);
        float2 xv = __half22float2(*(const __half2*)&S[(size_t)e.x * 64 + lane2]);
        ax += v * xv.x; ay += v * xv.y;
    }
}

// ---------------- gather SpMM steps (fp16 out for NP=1,2; fp32 s3 for NP=3), grid.y = meta ----------------
template<int NP>
__global__ void spmm_gather_kernel(const int* __restrict__ idxes_seq,
                                   const int* __restrict__ idxes_res) {
    int m = blockIdx.y;
    int gid = blockIdx.x * 256 + threadIdx.x;
    int row = gid >> 5;
    if (row >= NN) return;
    int lane2 = (threadIdx.x & 31) * 2;
    const int* seq = idxes_seq + m * 3;
    const int* res = idxes_res + m * 3;

    float ax = 0.f, ay = 0.f;
    if (NP == 1) {
        gath_pass(st_ptr(m, 0), seq[0], row, lane2, ax, ay);
    } else if (NP == 2) {
        gath_pass(st_ptr(m, 1), seq[1], row, lane2, ax, ay);
        gath_pass(st_ptr(m, 0), res[0], row, lane2, ax, ay);
    } else {
        gath_pass(st_ptr(m, 2), seq[2], row, lane2, ax, ay);
        gath_pass(st_ptr(m, 0), res[1], row, lane2, ax, ay);
        gath_pass(st_ptr(m, 1), res[2], row, lane2, ax, ay);
    }
    if (NP == 3) {
        *(float2*)&g_s3[m][(size_t)row * 64 + lane2] = make_float2(ax, ay);
    } else {
        __half* D = (__half*)st_ptr(m, NP);
        *(__half2*)&D[(size_t)row * 64 + lane2] = __floats2half2_rn(ax, ay);
    }
}

// ---------------- layernorm + exact gelu + attention logit; grid.y = meta ----------------
__global__ void post_kernel(const float* __restrict__ norm_g, const float* __restrict__ norm_b,
                            const float* __restrict__ A1, const float* __restrict__ b1,
                            const float* __restrict__ a2, const float* __restrict__ b2) {
    __shared__ float A1s[64][68];
    __shared__ float hs[8][68];
    __shared__ float b1s[64];
    __shared__ float a2s[64];
    int meta = blockIdx.y;
    const float* gvec = norm_g + meta * 64;
    const float* bvec = norm_b + meta * 64;
    int t = threadIdx.x;
    for (int i = t; i < 4096; i += 256) {
        int a = i >> 6, k = i & 63;
        A1s[a][k] = A1[i];
    }
    if (t < 64) { b1s[t] = b1[t]; a2s[t] = a2[t]; }
    __syncthreads();

    int w = t >> 5;
    int lane = t & 31;
    int node = blockIdx.x * 8 + w;
    if (node >= NN) return;

    float* T = g_t[meta];
    const float* S = g_s3[meta];

    float h0 = S[(size_t)node * 64 + lane];
    float h1 = S[(size_t)node * 64 + lane + 32];
    float mu = warp_sum(h0 + h1) * (1.0f / 64.0f);
    float d0 = h0 - mu, d1 = h1 - mu;
    float var = warp_sum(d0 * d0 + d1 * d1) * (1.0f / 64.0f);
    float rstd = rsqrtf(var + 1e-5f);
    float n0 = d0 * rstd * gvec[lane] + bvec[lane];
    float n1 = d1 * rstd * gvec[lane + 32] + bvec[lane + 32];
    float ge0 = 0.5f * n0 * (1.0f + erff(n0 * 0.70710678118654752f));
    float ge1 = 0.5f * n1 * (1.0f + erff(n1 * 0.70710678118654752f));
    T[(size_t)node * 64 + lane] = ge0;
    T[(size_t)node * 64 + lane + 32] = ge1;
    hs[w][lane] = ge0;
    hs[w][lane + 32] = ge1;
    __syncwarp();

    float part = 0.f;
    #pragma unroll
    for (int half = 0; half < 2; half++) {
        int a = lane + half * 32;
        float acc = b1s[a];
        #pragma unroll
        for (int k4 = 0; k4 < 16; k4++) {
            float4 wv = *(const float4*)&A1s[a][k4 * 4];
            float4 hv = *(const float4*)&hs[w][k4 * 4];
            acc += wv.x * hv.x + wv.y * hv.y + wv.z * hv.z + wv.w * hv.w;
        }
        part += tanhf(acc) * a2s[a];
    }
    part = warp_sum(part);
    if (lane == 0) g_logits[node * 2 + meta] = part + b2[0];
}

// ---------------- 2-way softmax over metas + weighted sum -> out ----------------
__global__ void mix_kernel(float* __restrict__ out) {
    int idx = blockIdx.x * 256 + threadIdx.x;
    if (idx >= NN * 16) return;
    int node = idx >> 4, q = idx & 15;
    float l0 = g_logits[node * 2 + 0];
    float l1 = g_logits[node * 2 + 1];
    float mx = fmaxf(l0, l1);
    float e0 = expf(l0 - mx), e1 = expf(l1 - mx);
    float inv = 1.0f / (e0 + e1);
    float w0 = e0 * inv, w1 = e1 * inv;
    float4 a = *(const float4*)&g_t[0][(size_t)node * 64 + q * 4];
    float4 b = *(const float4*)&g_t[1][(size_t)node * 64 + q * 4];
    *(float4*)&out[(size_t)node * 64 + q * 4] =
        make_float4(w0 * a.x + w1 * b.x, w0 * a.y + w1 * b.y,
                    w0 * a.z + w1 * b.z, w0 * a.w + w1 * b.w);
}

extern "C" void kernel_launch(void* const* d_in, const int* in_sizes, int n_in,
                              void* d_out, int out_size) {
    const float* feats0      = (const float*)d_in[0];
    const float* feats1      = (const float*)d_in[1];
    const float* feats2      = (const float*)d_in[2];
    const float* ws_W        = (const float*)d_in[3];
    const float* ws_b        = (const float*)d_in[4];
    const float* adj_vals    = (const float*)d_in[5];
    const float* cell_aff_W  = (const float*)d_in[6];
    const float* cell_aff_b  = (const float*)d_in[7];
    const float* cell_norm_g = (const float*)d_in[8];
    const float* cell_norm_b = (const float*)d_in[9];
    const float* attn1_W     = (const float*)d_in[10];
    const float* attn1_b     = (const float*)d_in[11];
    const float* attn2_W     = (const float*)d_in[12];
    const float* attn2_b     = (const float*)d_in[13];
    // d_in[14] = node_types (contiguous blocks; unused)
    const int* adj_rows      = (const int*)d_in[15];
    const int* adj_cols      = (const int*)d_in[16];
    const int* idxes_seq     = (const int*)d_in[17];   // [2,3]
    const int* idxes_res     = (const int*)d_in[18];   // [2,3]
    float* out = (float*)d_out;

    const int S0_BLOCKS     = (NPT + 63) / 64;
    const int EDGE16_BLOCKS = (NADJ * NNZC / 16 + 255) / 256;
    const int CNT_BLOCKS    = (NADJ * NN + 255) / 256;
    const int GATH_BLOCKS   = (NN * 32 + 255) / 256;
    const int POST_BLOCKS   = (NN + 7) / 8;
    const int MIX_BLOCKS    = (NN * 16 + 255) / 256;

    // fork a second stream off the (possibly capturing) default stream
    cudaStream_t s2;
    cudaStreamCreate(&s2);
    cudaEvent_t eFork, eJoin;
    cudaEventCreateWithFlags(&eFork, cudaEventDisableTiming);
    cudaEventCreateWithFlags(&eJoin, cudaEventDisableTiming);
    cudaEventRecord(eFork, 0);
    cudaStreamWaitEvent(s2, eFork, 0);

    // ---- branch B (s2): composed weights + fused s0 (both metas) ----
    wcomb_kernel<<<6, 256, 0, s2>>>(cell_aff_W, cell_aff_b, ws_W, ws_b);
    s0_kernel<<<dim3(S0_BLOCKS, 3), 256, 0, s2>>>(feats0, feats1, feats2);

    // ---- branch A (default stream): CSR build ----
    zero_counts_kernel<<<CNT_BLOCKS, 256>>>();
    hist_kernel<<<EDGE16_BLOCKS, 256>>>(adj_rows);
    scanA_kernel<<<dim3(NT, NADJ), 1024>>>();
    scanB_kernel<<<NADJ, 128>>>();
    scanC_kernel<<<dim3(NT, NADJ), 1024>>>();
    scatter_kernel<<<EDGE16_BLOCKS, 256>>>(adj_rows, adj_cols, adj_vals);

    // join: gathers need both CSR (branch A) and s0 (branch B)
    cudaEventRecord(eJoin, s2);
    cudaStreamWaitEvent(0, eJoin, 0);

    // ---- state chain, both metas per launch ----
    spmm_gather_kernel<1><<<dim3(GATH_BLOCKS, 2), 256>>>(idxes_seq, idxes_res);
    spmm_gather_kernel<2><<<dim3(GATH_BLOCKS, 2), 256>>>(idxes_seq, idxes_res);
    spmm_gather_kernel<3><<<dim3(GATH_BLOCKS, 2), 256>>>(idxes_seq, idxes_res);

    // ---- post (both metas) + mix ----
    post_kernel<<<dim3(POST_BLOCKS, 2), 256>>>(cell_norm_g, cell_norm_b,
                                               attn1_W, attn1_b, attn2_W, attn2_b);
    mix_kernel<<<MIX_BLOCKS, 256>>>(out);

    cudaEventDestroy(eFork);
    cudaEventDestroy(eJoin);
    cudaStreamDestroy(s2);
}

// round 13
// speedup vs baseline: 1.3603x; 1.0165x over previous
#include <cuda_runtime.h>
#include <cuda_fp16.h>
#include <math.h>

#define NN   99000
#define NH   64
#define NNZC 1584000
#define NADJ 6
#define NPT  33000
#define NT   97          // scan tiles per adjacency: ceil(99000/1024)

// ---------------- scratch (device globals; no runtime allocation) ----------------
__device__ __half g_st[2][3][NN * NH];   // fp16 states s0,s1,s2 per meta
__device__ float  g_s3[2][NN * NH];      // fp32 final state per meta (red.add target)
__device__ float  g_t[2][NN * NH];       // gelu output per meta
__device__ float  g_logits[NN * 2];
__device__ float  g_Wc[2][3][NH * NH];   // composed weights, transposed: [k_in*64 + i_out]
__device__ float  g_bc[2][3][NH];        // composed biases

// CSR scratch
__device__ int  g_cursor[NADJ * NN];
__device__ int  g_rowptr[NADJ * (NN + 1)];
__device__ int  g_tilesum[NADJ * NT];
__device__ int  g_tileoff[NADJ * NT];
__device__ int2 g_pack[(size_t)NADJ * NNZC];  // (col, val bits) sorted by row

__device__ __forceinline__ const __half* st_ptr(int m, int id) {
    return g_st[m][id];
}

__device__ __forceinline__ float warp_sum(float v) {
    #pragma unroll
    for (int o = 16; o > 0; o >>= 1) v += __shfl_xor_sync(0xffffffffu, v, o);
    return v;
}

__device__ __forceinline__ void red_add_v2(float* p, float x, float y) {
    asm volatile("red.global.add.v2.f32 [%0], {%1,%2};"
                 :: "l"(p), "f"(x), "f"(y) : "memory");
}

// ---------------- CSR build ----------------
__global__ void zero_counts_kernel() {
    int i = blockIdx.x * 256 + threadIdx.x;
    if (i < NADJ * NN) g_cursor[i] = 0;
}

__global__ void hist_kernel(const int* __restrict__ rows) {
    int i = blockIdx.x * 256 + threadIdx.x;
    if (i >= NADJ * NNZC / 16) return;
    int a = (i * 16) / NNZC;
    int* cnt = g_cursor + a * NN;
    #pragma unroll
    for (int h = 0; h < 4; h++) {
        int4 r = *(const int4*)&rows[i * 16 + h * 4];
        atomicAdd(&cnt[r.x], 1); atomicAdd(&cnt[r.y], 1);
        atomicAdd(&cnt[r.z], 1); atomicAdd(&cnt[r.w], 1);
    }
}

__global__ void scanA_kernel() {
    __shared__ int sh[32];
    int a = blockIdx.y, tile = blockIdx.x;
    int idx = tile * 1024 + threadIdx.x;
    int lane = threadIdx.x & 31, wid = threadIdx.x >> 5;
    int v = (idx < NN) ? g_cursor[a * NN + idx] : 0;
    int s = v;
    #pragma unroll
    for (int o = 1; o < 32; o <<= 1) {
        int n = __shfl_up_sync(0xffffffffu, s, o);
        if (lane >= o) s += n;
    }
    if (lane == 31) sh[wid] = s;
    __syncthreads();
    if (wid == 0) {
        int w = sh[lane];
        #pragma unroll
        for (int o = 1; o < 32; o <<= 1) {
            int n = __shfl_up_sync(0xffffffffu, w, o);
            if (lane >= o) w += n;
        }
        sh[lane] = w;
    }
    __syncthreads();
    int incl = s + ((wid > 0) ? sh[wid - 1] : 0);
    if (idx < NN) g_rowptr[a * (NN + 1) + idx] = incl - v;
    if (threadIdx.x == 1023) g_tilesum[a * NT + tile] = incl;
}

__global__ void scanB_kernel() {
    __shared__ int sh[4];
    int a = blockIdx.x, t = threadIdx.x;
    int lane = t & 31, wid = t >> 5;
    int orig = (t < NT) ? g_tilesum[a * NT + t] : 0;
    int s = orig;
    #pragma unroll
    for (int o = 1; o < 32; o <<= 1) {
        int n = __shfl_up_sync(0xffffffffu, s, o);
        if (lane >= o) s += n;
    }
    if (lane == 31) sh[wid] = s;
    __syncthreads();
    int add = 0;
    for (int w = 0; w < wid; w++) add += sh[w];
    int incl = s + add;
    if (t < NT) g_tileoff[a * NT + t] = incl - orig;
    if (t == NT - 1) g_rowptr[a * (NN + 1) + NN] = incl;
}

__global__ void scanC_kernel() {
    int a = blockIdx.y;
    int idx = blockIdx.x * 1024 + threadIdx.x;
    if (idx >= NN) return;
    int off = g_tileoff[a * NT + blockIdx.x];
    int e = g_rowptr[a * (NN + 1) + idx] + off;
    g_rowptr[a * (NN + 1) + idx] = e;
    g_cursor[a * NN + idx] = e;
}

__global__ void scatter_kernel(const int* __restrict__ rows, const int* __restrict__ cols,
                               const float* __restrict__ vals) {
    int i = blockIdx.x * 256 + threadIdx.x;
    if (i >= NADJ * NNZC / 16) return;
    int a = (i * 16) / NNZC;
    int* cur = g_cursor + a * NN;
    int2* pk = (int2*)(g_pack + (size_t)a * NNZC);
    #pragma unroll
    for (int h = 0; h < 4; h++) {
        int base = i * 16 + h * 4;
        int4 r = *(const int4*)&rows[base];
        int4 c = *(const int4*)&cols[base];
        float4 v = *(const float4*)&vals[base];
        int p0 = atomicAdd(&cur[r.x], 1);
        int p1 = atomicAdd(&cur[r.y], 1);
        int p2 = atomicAdd(&cur[r.z], 1);
        int p3 = atomicAdd(&cur[r.w], 1);
        pk[p0] = make_int2(c.x, __float_as_int(v.x));
        pk[p1] = make_int2(c.y, __float_as_int(v.y));
        pk[p2] = make_int2(c.z, __float_as_int(v.z));
        pk[p3] = make_int2(c.w, __float_as_int(v.w));
    }
}

// ---------------- weight composition ----------------
__global__ void wcomb_kernel(const float* __restrict__ cW, const float* __restrict__ cb,
                             const float* __restrict__ wsW, const float* __restrict__ wsb) {
    __shared__ float cs[64][65];
    __shared__ float ws[64][65];
    int blk = blockIdx.x;
    int m = blk / 3;
    int t = blk % 3;
    int tid = threadIdx.x;
    for (int i = tid; i < 4096; i += 256) {
        int r = i >> 6, c = i & 63;
        cs[r][c] = cW[m * 4096 + i];
        ws[r][c] = wsW[t * 4096 + i];
    }
    __syncthreads();
    for (int e = tid; e < 4096; e += 256) {
        int i = e >> 6, k = e & 63;
        float acc = 0.f;
        #pragma unroll
        for (int q = 0; q < 64; q++) acc += cs[i][q] * ws[q][k];
        g_Wc[m][t][k * 64 + i] = acc;
    }
    if (tid < 64) {
        float acc = cb[m * 64 + tid];
        #pragma unroll
        for (int q = 0; q < 64; q++) acc += cs[tid][q] * wsb[t * 64 + q];
        g_bc[m][t][tid] = acc;
    }
}

// ---------------- fused s0: both metas from feats directly ----------------
__global__ void s0_kernel(const float* __restrict__ f0, const float* __restrict__ f1,
                          const float* __restrict__ f2) {
    __shared__ float Xs[64][68];
    __shared__ float Wt[64][64];
    __shared__ float bs[64];
    int type = blockIdx.y;
    const float* X = (type == 0) ? f0 : (type == 1) ? f1 : f2;
    int t = threadIdx.x;
    int lrow0 = blockIdx.x * 64;
    for (int i = t; i < 1024; i += 256) {
        int r = i >> 4, q = i & 15;
        float4 v = make_float4(0.f, 0.f, 0.f, 0.f);
        if (lrow0 + r < NPT) v = *(const float4*)&X[(size_t)(lrow0 + r) * 64 + q * 4];
        *(float4*)&Xs[r][q * 4] = v;
    }
    int nd = t >> 3;
    int cg = (t & 7) * 8;
    #pragma unroll
    for (int m = 0; m < 2; m++) {
        __syncthreads();
        for (int i = t; i < 4096; i += 256) ((float*)Wt)[i] = g_Wc[m][type][i];
        if (t < 64) bs[t] = g_bc[m][type][t];
        __syncthreads();
        float acc0[8], acc1[8];
        #pragma unroll
        for (int j = 0; j < 8; j++) { acc0[j] = bs[cg + j]; acc1[j] = bs[cg + j]; }
        #pragma unroll
        for (int k = 0; k < 64; k++) {
            float x0 = Xs[nd][k];
            float x1 = Xs[nd + 32][k];
            float4 w0 = *(const float4*)&Wt[k][cg];
            float4 w1 = *(const float4*)&Wt[k][cg + 4];
            acc0[0] += x0 * w0.x; acc0[1] += x0 * w0.y; acc0[2] += x0 * w0.z; acc0[3] += x0 * w0.w;
            acc0[4] += x0 * w1.x; acc0[5] += x0 * w1.y; acc0[6] += x0 * w1.z; acc0[7] += x0 * w1.w;
            acc1[0] += x1 * w0.x; acc1[1] += x1 * w0.y; acc1[2] += x1 * w0.z; acc1[3] += x1 * w0.w;
            acc1[4] += x1 * w1.x; acc1[5] += x1 * w1.y; acc1[6] += x1 * w1.z; acc1[7] += x1 * w1.w;
        }
        __half* D = (__half*)g_st[m][0];
        int r0 = type * NPT + lrow0 + nd;
        int r1 = r0 + 32;
        if (lrow0 + nd < NPT) {
            __half2* yp = (__half2*)&D[(size_t)r0 * 64 + cg];
            yp[0] = __floats2half2_rn(acc0[0], acc0[1]);
            yp[1] = __floats2half2_rn(acc0[2], acc0[3]);
            yp[2] = __floats2half2_rn(acc0[4], acc0[5]);
            yp[3] = __floats2half2_rn(acc0[6], acc0[7]);
        }
        if (lrow0 + nd + 32 < NPT) {
            __half2* yp = (__half2*)&D[(size_t)r1 * 64 + cg];
            yp[0] = __floats2half2_rn(acc1[0], acc1[1]);
            yp[1] = __floats2half2_rn(acc1[2], acc1[3]);
            yp[2] = __floats2half2_rn(acc1[4], acc1[5]);
            yp[3] = __floats2half2_rn(acc1[6], acc1[7]);
        }
    }
}

// ---------------- zero s3 (both metas) ----------------
__global__ void zero_s3_kernel() {
    int i = blockIdx.x * 256 + threadIdx.x;
    if (i < NN * NH * 2 / 4) ((float4*)g_s3)[i] = make_float4(0.f, 0.f, 0.f, 0.f);
}

// ---------------- gather core (int2 metadata, 8-edge batches) ----------------
__device__ __forceinline__ void gath_pass(const __half* __restrict__ S, int aidx,
                                          int row, int lane2, float& ax, float& ay) {
    const int* rp = g_rowptr + aidx * (NN + 1);
    int j   = rp[row];
    int end = rp[row + 1];
    const int2* __restrict__ pk = g_pack + (size_t)aidx * NNZC;

    for (; j + 8 <= end; j += 8) {
        int2 e0 = pk[j],     e1 = pk[j + 1], e2 = pk[j + 2], e3 = pk[j + 3];
        int2 e4 = pk[j + 4], e5 = pk[j + 5], e6 = pk[j + 6], e7 = pk[j + 7];
        float2 x0 = __half22float2(*(const __half2*)&S[(size_t)e0.x * 64 + lane2]);
        float2 x1 = __half22float2(*(const __half2*)&S[(size_t)e1.x * 64 + lane2]);
        float2 x2 = __half22float2(*(const __half2*)&S[(size_t)e2.x * 64 + lane2]);
        float2 x3 = __half22float2(*(const __half2*)&S[(size_t)e3.x * 64 + lane2]);
        float2 x4 = __half22float2(*(const __half2*)&S[(size_t)e4.x * 64 + lane2]);
        float2 x5 = __half22float2(*(const __half2*)&S[(size_t)e5.x * 64 + lane2]);
        float2 x6 = __half22float2(*(const __half2*)&S[(size_t)e6.x * 64 + lane2]);
        float2 x7 = __half22float2(*(const __half2*)&S[(size_t)e7.x * 64 + lane2]);
        ax += __int_as_float(e0.y) * x0.x; ay += __int_as_float(e0.y) * x0.y;
        ax += __int_as_float(e1.y) * x1.x; ay += __int_as_float(e1.y) * x1.y;
        ax += __int_as_float(e2.y) * x2.x; ay += __int_as_float(e2.y) * x2.y;
        ax += __int_as_float(e3.y) * x3.x; ay += __int_as_float(e3.y) * x3.y;
        ax += __int_as_float(e4.y) * x4.x; ay += __int_as_float(e4.y) * x4.y;
        ax += __int_as_float(e5.y) * x5.x; ay += __int_as_float(e5.y) * x5.y;
        ax += __int_as_float(e6.y) * x6.x; ay += __int_as_float(e6.y) * x6.y;
        ax += __int_as_float(e7.y) * x7.x; ay += __int_as_float(e7.y) * x7.y;
    }
    for (; j + 4 <= end; j += 4) {
        int2 e0 = pk[j], e1 = pk[j + 1], e2 = pk[j + 2], e3 = pk[j + 3];
        float2 x0 = __half22float2(*(const __half2*)&S[(size_t)e0.x * 64 + lane2]);
        float2 x1 = __half22float2(*(const __half2*)&S[(size_t)e1.x * 64 + lane2]);
        float2 x2 = __half22float2(*(const __half2*)&S[(size_t)e2.x * 64 + lane2]);
        float2 x3 = __half22float2(*(const __half2*)&S[(size_t)e3.x * 64 + lane2]);
        ax += __int_as_float(e0.y) * x0.x; ay += __int_as_float(e0.y) * x0.y;
        ax += __int_as_float(e1.y) * x1.x; ay += __int_as_float(e1.y) * x1.y;
        ax += __int_as_float(e2.y) * x2.x; ay += __int_as_float(e2.y) * x2.y;
        ax += __int_as_float(e3.y) * x3.x; ay += __int_as_float(e3.y) * x3.y;
    }
    for (; j < end; j++) {
        int2 e = pk[j];
        float v = __int_as_float(e.y);
        float2 xv = __half22float2(*(const __half2*)&S[(size_t)e.x * 64 + lane2]);
        ax += v * xv.x; ay += v * xv.y;
    }
}

// ---------------- g1 / g2: fp16-out gathers, grid.y = meta ----------------
template<int NP>
__global__ void spmm_gather_kernel(const int* __restrict__ idxes_seq,
                                   const int* __restrict__ idxes_res) {
    int m = blockIdx.y;
    int gid = blockIdx.x * 256 + threadIdx.x;
    int row = gid >> 5;
    if (row >= NN) return;
    int lane2 = (threadIdx.x & 31) * 2;
    const int* seq = idxes_seq + m * 3;
    const int* res = idxes_res + m * 3;

    float ax = 0.f, ay = 0.f;
    if (NP == 1) {
        gath_pass(st_ptr(m, 0), seq[0], row, lane2, ax, ay);
    } else {
        gath_pass(st_ptr(m, 1), seq[1], row, lane2, ax, ay);
        gath_pass(st_ptr(m, 0), res[0], row, lane2, ax, ay);
    }
    __half* D = (__half*)st_ptr(m, NP);
    *(__half2*)&D[(size_t)row * 64 + lane2] = __floats2half2_rn(ax, ay);
}

// ---------------- single s3 pass: s3 += A[idx[m*3+off]] . s_src, red.add ----------------
__global__ void spmm_pass_kernel(const int* __restrict__ idx_arr, int off, int src_id) {
    int m = blockIdx.y;
    int gid = blockIdx.x * 256 + threadIdx.x;
    int row = gid >> 5;
    if (row >= NN) return;
    int lane2 = (threadIdx.x & 31) * 2;
    int aidx = idx_arr[m * 3 + off];

    float ax = 0.f, ay = 0.f;
    gath_pass(st_ptr(m, src_id), aidx, row, lane2, ax, ay);
    red_add_v2(&g_s3[m][(size_t)row * 64 + lane2], ax, ay);
}

// ---------------- layernorm + exact gelu + attention logit; grid.y = meta ----------------
__global__ void post_kernel(const float* __restrict__ norm_g, const float* __restrict__ norm_b,
                            const float* __restrict__ A1, const float* __restrict__ b1,
                            const float* __restrict__ a2, const float* __restrict__ b2) {
    __shared__ float A1s[64][68];
    __shared__ float hs[8][68];
    __shared__ float b1s[64];
    __shared__ float a2s[64];
    int meta = blockIdx.y;
    const float* gvec = norm_g + meta * 64;
    const float* bvec = norm_b + meta * 64;
    int t = threadIdx.x;
    for (int i = t; i < 4096; i += 256) {
        int a = i >> 6, k = i & 63;
        A1s[a][k] = A1[i];
    }
    if (t < 64) { b1s[t] = b1[t]; a2s[t] = a2[t]; }
    __syncthreads();

    int w = t >> 5;
    int lane = t & 31;
    int node = blockIdx.x * 8 + w;
    if (node >= NN) return;

    float* T = g_t[meta];
    const float* S = g_s3[meta];

    float h0 = S[(size_t)node * 64 + lane];
    float h1 = S[(size_t)node * 64 + lane + 32];
    float mu = warp_sum(h0 + h1) * (1.0f / 64.0f);
    float d0 = h0 - mu, d1 = h1 - mu;
    float var = warp_sum(d0 * d0 + d1 * d1) * (1.0f / 64.0f);
    float rstd = rsqrtf(var + 1e-5f);
    float n0 = d0 * rstd * gvec[lane] + bvec[lane];
    float n1 = d1 * rstd * gvec[lane + 32] + bvec[lane + 32];
    float ge0 = 0.5f * n0 * (1.0f + erff(n0 * 0.70710678118654752f));
    float ge1 = 0.5f * n1 * (1.0f + erff(n1 * 0.70710678118654752f));
    T[(size_t)node * 64 + lane] = ge0;
    T[(size_t)node * 64 + lane + 32] = ge1;
    hs[w][lane] = ge0;
    hs[w][lane + 32] = ge1;
    __syncwarp();

    float part = 0.f;
    #pragma unroll
    for (int half = 0; half < 2; half++) {
        int a = lane + half * 32;
        float acc = b1s[a];
        #pragma unroll
        for (int k4 = 0; k4 < 16; k4++) {
            float4 wv = *(const float4*)&A1s[a][k4 * 4];
            float4 hv = *(const float4*)&hs[w][k4 * 4];
            acc += wv.x * hv.x + wv.y * hv.y + wv.z * hv.z + wv.w * hv.w;
        }
        part += tanhf(acc) * a2s[a];
    }
    part = warp_sum(part);
    if (lane == 0) g_logits[node * 2 + meta] = part + b2[0];
}

// ---------------- 2-way softmax over metas + weighted sum -> out ----------------
__global__ void mix_kernel(float* __restrict__ out) {
    int idx = blockIdx.x * 256 + threadIdx.x;
    if (idx >= NN * 16) return;
    int node = idx >> 4, q = idx & 15;
    float l0 = g_logits[node * 2 + 0];
    float l1 = g_logits[node * 2 + 1];
    float mx = fmaxf(l0, l1);
    float e0 = expf(l0 - mx), e1 = expf(l1 - mx);
    float inv = 1.0f / (e0 + e1);
    float w0 = e0 * inv, w1 = e1 * inv;
    float4 a = *(const float4*)&g_t[0][(size_t)node * 64 + q * 4];
    float4 b = *(const float4*)&g_t[1][(size_t)node * 64 + q * 4];
    *(float4*)&out[(size_t)node * 64 + q * 4] =
        make_float4(w0 * a.x + w1 * b.x, w0 * a.y + w1 * b.y,
                    w0 * a.z + w1 * b.z, w0 * a.w + w1 * b.w);
}

extern "C" void kernel_launch(void* const* d_in, const int* in_sizes, int n_in,
                              void* d_out, int out_size) {
    const float* feats0      = (const float*)d_in[0];
    const float* feats1      = (const float*)d_in[1];
    const float* feats2      = (const float*)d_in[2];
    const float* ws_W        = (const float*)d_in[3];
    const float* ws_b        = (const float*)d_in[4];
    const float* adj_vals    = (const float*)d_in[5];
    const float* cell_aff_W  = (const float*)d_in[6];
    const float* cell_aff_b  = (const float*)d_in[7];
    const float* cell_norm_g = (const float*)d_in[8];
    const float* cell_norm_b = (const float*)d_in[9];
    const float* attn1_W     = (const float*)d_in[10];
    const float* attn1_b     = (const float*)d_in[11];
    const float* attn2_W     = (const float*)d_in[12];
    const float* attn2_b     = (const float*)d_in[13];
    // d_in[14] = node_types (contiguous blocks; unused)
    const int* adj_rows      = (const int*)d_in[15];
    const int* adj_cols      = (const int*)d_in[16];
    const int* idxes_seq     = (const int*)d_in[17];   // [2,3]
    const int* idxes_res     = (const int*)d_in[18];   // [2,3]
    float* out = (float*)d_out;

    const int S0_BLOCKS     = (NPT + 63) / 64;
    const int EDGE16_BLOCKS = (NADJ * NNZC / 16 + 255) / 256;
    const int CNT_BLOCKS    = (NADJ * NN + 255) / 256;
    const int GATH_BLOCKS   = (NN * 32 + 255) / 256;
    const int ZS3_BLOCKS    = (NN * NH * 2 / 4 + 255) / 256;
    const int POST_BLOCKS   = (NN + 7) / 8;
    const int MIX_BLOCKS    = (NN * 16 + 255) / 256;

    cudaStream_t s2;
    cudaStreamCreate(&s2);
    cudaEvent_t eFork, eA, eB, eG1, eRes;
    cudaEventCreateWithFlags(&eFork, cudaEventDisableTiming);
    cudaEventCreateWithFlags(&eA, cudaEventDisableTiming);
    cudaEventCreateWithFlags(&eB, cudaEventDisableTiming);
    cudaEventCreateWithFlags(&eG1, cudaEventDisableTiming);
    cudaEventCreateWithFlags(&eRes, cudaEventDisableTiming);
    cudaEventRecord(eFork, 0);
    cudaStreamWaitEvent(s2, eFork, 0);

    // ---- branch B (s2): weights + s0 + zero s3 ----
    wcomb_kernel<<<6, 256, 0, s2>>>(cell_aff_W, cell_aff_b, ws_W, ws_b);
    s0_kernel<<<dim3(S0_BLOCKS, 3), 256, 0, s2>>>(feats0, feats1, feats2);
    zero_s3_kernel<<<ZS3_BLOCKS, 256, 0, s2>>>();
    cudaEventRecord(eB, s2);

    // ---- branch A (default stream): CSR build ----
    zero_counts_kernel<<<CNT_BLOCKS, 256>>>();
    hist_kernel<<<EDGE16_BLOCKS, 256>>>(adj_rows);
    scanA_kernel<<<dim3(NT, NADJ), 1024>>>();
    scanB_kernel<<<NADJ, 128>>>();
    scanC_kernel<<<dim3(NT, NADJ), 1024>>>();
    scatter_kernel<<<EDGE16_BLOCKS, 256>>>(adj_rows, adj_cols, adj_vals);
    cudaEventRecord(eA, 0);

    // cross-join: stream0 needs s0+zero(eB); s2 needs CSR(eA)
    cudaStreamWaitEvent(0, eB, 0);
    cudaStreamWaitEvent(s2, eA, 0);

    // ---- stage 1: g1 (s1 = A[seq0] s0)  ||  res1 pass (s3 += A[res1] s0) ----
    spmm_gather_kernel<1><<<dim3(GATH_BLOCKS, 2), 256>>>(idxes_seq, idxes_res);
    cudaEventRecord(eG1, 0);
    spmm_pass_kernel<<<dim3(GATH_BLOCKS, 2), 256, 0, s2>>>(idxes_res, 1, 0);

    // ---- stage 2: g2 (s2 = A[seq1] s1 + A[res0] s0)  ||  res2 pass (s3 += A[res2] s1) ----
    spmm_gather_kernel<2><<<dim3(GATH_BLOCKS, 2), 256>>>(idxes_seq, idxes_res);
    cudaStreamWaitEvent(s2, eG1, 0);
    spmm_pass_kernel<<<dim3(GATH_BLOCKS, 2), 256, 0, s2>>>(idxes_res, 2, 1);
    cudaEventRecord(eRes, s2);

    // ---- stage 3: s3 += A[seq2] s2, then post + mix ----
    spmm_pass_kernel<<<dim3(GATH_BLOCKS, 2), 256>>>(idxes_seq, 2, 2);
    cudaStreamWaitEvent(0, eRes, 0);
    post_kernel<<<dim3(POST_BLOCKS, 2), 256>>>(cell_norm_g, cell_norm_b,
                                               attn1_W, attn1_b, attn2_W, attn2_b);
    mix_kernel<<<MIX_BLOCKS, 256>>>(out);

    cudaEventDestroy(eFork);
    cudaEventDestroy(eA);
    cudaEventDestroy(eB);
    cudaEventDestroy(eG1);
    cudaEventDestroy(eRes);
    cudaStreamDestroy(s2);
}

// round 15
// speedup vs baseline: 1.6029x; 1.1784x over previous
#include <cuda_runtime.h>
#include <cuda_fp16.h>
#include <math.h>

#define NN   99000
#define NH   64
#define NNZC 1584000
#define NADJ 6
#define NPT  33000
#define NT   97          // scan tiles per adjacency: ceil(99000/1024)

// ---------------- scratch (device globals; no runtime allocation) ----------------
__device__ __half g_st[2][3][NN * NH];   // fp16 states s0,s1,s2 per meta
__device__ float  g_s3[2][NN * NH];      // fp32 final state per meta (red.add target)
__device__ float  g_t[2][NN * NH];       // gelu output per meta
__device__ float  g_logits[NN * 2];
__device__ float  g_Wc[2][3][NH * NH];   // composed weights, transposed: [k_in*64 + i_out]
__device__ float  g_bc[2][3][NH];        // composed biases

// CSR scratch
__device__ int  g_cursor[NADJ * NN];
__device__ int  g_rowptr[NADJ * (NN + 1)];
__device__ int  g_tilesum[NADJ * NT];
__device__ int  g_tileoff[NADJ * NT];
__device__ int2 g_pack[(size_t)NADJ * NNZC];  // (col, val bits) sorted by row

__device__ __forceinline__ const __half* st_ptr(int m, int id) {
    return g_st[m][id];
}

__device__ __forceinline__ float warp_sum(float v) {
    #pragma unroll
    for (int o = 16; o > 0; o >>= 1) v += __shfl_xor_sync(0xffffffffu, v, o);
    return v;
}

__device__ __forceinline__ void red_add_v4(float* p, float a, float b, float c, float d) {
    asm volatile("red.global.add.v4.f32 [%0], {%1,%2,%3,%4};"
                 :: "l"(p), "f"(a), "f"(b), "f"(c), "f"(d) : "memory");
}

// ---------------- CSR build ----------------
__global__ void zero_counts_kernel() {
    int i = blockIdx.x * 256 + threadIdx.x;
    if (i < NADJ * NN) g_cursor[i] = 0;
}

__global__ void hist_kernel(const int* __restrict__ rows) {
    int i = blockIdx.x * 256 + threadIdx.x;
    if (i >= NADJ * NNZC / 16) return;
    int a = (i * 16) / NNZC;
    int* cnt = g_cursor + a * NN;
    #pragma unroll
    for (int h = 0; h < 4; h++) {
        int4 r = *(const int4*)&rows[i * 16 + h * 4];
        atomicAdd(&cnt[r.x], 1); atomicAdd(&cnt[r.y], 1);
        atomicAdd(&cnt[r.z], 1); atomicAdd(&cnt[r.w], 1);
    }
}

__global__ void scanA_kernel() {
    __shared__ int sh[32];
    int a = blockIdx.y, tile = blockIdx.x;
    int idx = tile * 1024 + threadIdx.x;
    int lane = threadIdx.x & 31, wid = threadIdx.x >> 5;
    int v = (idx < NN) ? g_cursor[a * NN + idx] : 0;
    int s = v;
    #pragma unroll
    for (int o = 1; o < 32; o <<= 1) {
        int n = __shfl_up_sync(0xffffffffu, s, o);
        if (lane >= o) s += n;
    }
    if (lane == 31) sh[wid] = s;
    __syncthreads();
    if (wid == 0) {
        int w = sh[lane];
        #pragma unroll
        for (int o = 1; o < 32; o <<= 1) {
            int n = __shfl_up_sync(0xffffffffu, w, o);
            if (lane >= o) w += n;
        }
        sh[lane] = w;
    }
    __syncthreads();
    int incl = s + ((wid > 0) ? sh[wid - 1] : 0);
    if (idx < NN) g_rowptr[a * (NN + 1) + idx] = incl - v;
    if (threadIdx.x == 1023) g_tilesum[a * NT + tile] = incl;
}

__global__ void scanB_kernel() {
    __shared__ int sh[4];
    int a = blockIdx.x, t = threadIdx.x;
    int lane = t & 31, wid = t >> 5;
    int orig = (t < NT) ? g_tilesum[a * NT + t] : 0;
    int s = orig;
    #pragma unroll
    for (int o = 1; o < 32; o <<= 1) {
        int n = __shfl_up_sync(0xffffffffu, s, o);
        if (lane >= o) s += n;
    }
    if (lane == 31) sh[wid] = s;
    __syncthreads();
    int add = 0;
    for (int w = 0; w < wid; w++) add += sh[w];
    int incl = s + add;
    if (t < NT) g_tileoff[a * NT + t] = incl - orig;
    if (t == NT - 1) g_rowptr[a * (NN + 1) + NN] = incl;
}

__global__ void scanC_kernel() {
    int a = blockIdx.y;
    int idx = blockIdx.x * 1024 + threadIdx.x;
    if (idx >= NN) return;
    int off = g_tileoff[a * NT + blockIdx.x];
    int e = g_rowptr[a * (NN + 1) + idx] + off;
    g_rowptr[a * (NN + 1) + idx] = e;
    g_cursor[a * NN + idx] = e;
}

__global__ void scatter_kernel(const int* __restrict__ rows, const int* __restrict__ cols,
                               const float* __restrict__ vals) {
    int i = blockIdx.x * 256 + threadIdx.x;
    if (i >= NADJ * NNZC / 16) return;
    int a = (i * 16) / NNZC;
    int* cur = g_cursor + a * NN;
    int2* pk = (int2*)(g_pack + (size_t)a * NNZC);
    #pragma unroll
    for (int h = 0; h < 4; h++) {
        int base = i * 16 + h * 4;
        int4 r = *(const int4*)&rows[base];
        int4 c = *(const int4*)&cols[base];
        float4 v = *(const float4*)&vals[base];
        int p0 = atomicAdd(&cur[r.x], 1);
        int p1 = atomicAdd(&cur[r.y], 1);
        int p2 = atomicAdd(&cur[r.z], 1);
        int p3 = atomicAdd(&cur[r.w], 1);
        pk[p0] = make_int2(c.x, __float_as_int(v.x));
        pk[p1] = make_int2(c.y, __float_as_int(v.y));
        pk[p2] = make_int2(c.z, __float_as_int(v.z));
        pk[p3] = make_int2(c.w, __float_as_int(v.w));
    }
}

// ---------------- weight composition ----------------
__global__ void wcomb_kernel(const float* __restrict__ cW, const float* __restrict__ cb,
                             const float* __restrict__ wsW, const float* __restrict__ wsb) {
    __shared__ float cs[64][65];
    __shared__ float ws[64][65];
    int blk = blockIdx.x;
    int m = blk / 3;
    int t = blk % 3;
    int tid = threadIdx.x;
    for (int i = tid; i < 4096; i += 256) {
        int r = i >> 6, c = i & 63;
        cs[r][c] = cW[m * 4096 + i];
        ws[r][c] = wsW[t * 4096 + i];
    }
    __syncthreads();
    for (int e = tid; e < 4096; e += 256) {
        int i = e >> 6, k = e & 63;
        float acc = 0.f;
        #pragma unroll
        for (int q = 0; q < 64; q++) acc += cs[i][q] * ws[q][k];
        g_Wc[m][t][k * 64 + i] = acc;
    }
    if (tid < 64) {
        float acc = cb[m * 64 + tid];
        #pragma unroll
        for (int q = 0; q < 64; q++) acc += cs[tid][q] * wsb[t * 64 + q];
        g_bc[m][t][tid] = acc;
    }
}

// ---------------- fused s0: both metas from feats directly ----------------
__global__ void s0_kernel(const float* __restrict__ f0, const float* __restrict__ f1,
                          const float* __restrict__ f2) {
    __shared__ float Xs[64][68];
    __shared__ float Wt[64][64];
    __shared__ float bs[64];
    int type = blockIdx.y;
    const float* X = (type == 0) ? f0 : (type == 1) ? f1 : f2;
    int t = threadIdx.x;
    int lrow0 = blockIdx.x * 64;
    for (int i = t; i < 1024; i += 256) {
        int r = i >> 4, q = i & 15;
        float4 v = make_float4(0.f, 0.f, 0.f, 0.f);
        if (lrow0 + r < NPT) v = *(const float4*)&X[(size_t)(lrow0 + r) * 64 + q * 4];
        *(float4*)&Xs[r][q * 4] = v;
    }
    int nd = t >> 3;
    int cg = (t & 7) * 8;
    #pragma unroll
    for (int m = 0; m < 2; m++) {
        __syncthreads();
        for (int i = t; i < 4096; i += 256) ((float*)Wt)[i] = g_Wc[m][type][i];
        if (t < 64) bs[t] = g_bc[m][type][t];
        __syncthreads();
        float acc0[8], acc1[8];
        #pragma unroll
        for (int j = 0; j < 8; j++) { acc0[j] = bs[cg + j]; acc1[j] = bs[cg + j]; }
        #pragma unroll
        for (int k = 0; k < 64; k++) {
            float x0 = Xs[nd][k];
            float x1 = Xs[nd + 32][k];
            float4 w0 = *(const float4*)&Wt[k][cg];
            float4 w1 = *(const float4*)&Wt[k][cg + 4];
            acc0[0] += x0 * w0.x; acc0[1] += x0 * w0.y; acc0[2] += x0 * w0.z; acc0[3] += x0 * w0.w;
            acc0[4] += x0 * w1.x; acc0[5] += x0 * w1.y; acc0[6] += x0 * w1.z; acc0[7] += x0 * w1.w;
            acc1[0] += x1 * w0.x; acc1[1] += x1 * w0.y; acc1[2] += x1 * w0.z; acc1[3] += x1 * w0.w;
            acc1[4] += x1 * w1.x; acc1[5] += x1 * w1.y; acc1[6] += x1 * w1.z; acc1[7] += x1 * w1.w;
        }
        __half* D = (__half*)g_st[m][0];
        int r0 = type * NPT + lrow0 + nd;
        int r1 = r0 + 32;
        if (lrow0 + nd < NPT) {
            __half2* yp = (__half2*)&D[(size_t)r0 * 64 + cg];
            yp[0] = __floats2half2_rn(acc0[0], acc0[1]);
            yp[1] = __floats2half2_rn(acc0[2], acc0[3]);
            yp[2] = __floats2half2_rn(acc0[4], acc0[5]);
            yp[3] = __floats2half2_rn(acc0[6], acc0[7]);
        }
        if (lrow0 + nd + 32 < NPT) {
            __half2* yp = (__half2*)&D[(size_t)r1 * 64 + cg];
            yp[0] = __floats2half2_rn(acc1[0], acc1[1]);
            yp[1] = __floats2half2_rn(acc1[2], acc1[3]);
            yp[2] = __floats2half2_rn(acc1[4], acc1[5]);
            yp[3] = __floats2half2_rn(acc1[6], acc1[7]);
        }
    }
}

// ---------------- zero s3 (both metas) ----------------
__global__ void zero_s3_kernel() {
    int i = blockIdx.x * 256 + threadIdx.x;
    if (i < NN * NH * 2 / 4) ((float4*)g_s3)[i] = make_float4(0.f, 0.f, 0.f, 0.f);
}

// ---------------- gather core: half-warp per row, 4 halves per lane ----------------
// sub4 = (lane & 15) * 4 : this lane owns columns [sub4, sub4+4)
#define GEDGE(e, q)                                                     \
    {                                                                   \
        float v = __int_as_float((e).y);                                \
        float2 lo = __half22float2(*(const __half2*)&(q).x);            \
        float2 hi = __half22float2(*(const __half2*)&(q).y);            \
        a0 += v * lo.x; a1 += v * lo.y; a2 += v * hi.x; a3 += v * hi.y; \
    }

__device__ __forceinline__ void gath_pass2(const __half* __restrict__ S, int aidx,
                                           int row, int sub4,
                                           float& a0, float& a1, float& a2, float& a3) {
    const int* rp = g_rowptr + aidx * (NN + 1);
    int j   = rp[row];
    int end = rp[row + 1];
    const int2* __restrict__ pk = g_pack + (size_t)aidx * NNZC;

    for (; j + 4 <= end; j += 4) {
        int2 e0 = pk[j], e1 = pk[j + 1], e2 = pk[j + 2], e3 = pk[j + 3];
        int2 q0 = *(const int2*)&S[(size_t)e0.x * 64 + sub4];
        int2 q1 = *(const int2*)&S[(size_t)e1.x * 64 + sub4];
        int2 q2 = *(const int2*)&S[(size_t)e2.x * 64 + sub4];
        int2 q3 = *(const int2*)&S[(size_t)e3.x * 64 + sub4];
        GEDGE(e0, q0) GEDGE(e1, q1) GEDGE(e2, q2) GEDGE(e3, q3)
    }
    for (; j < end; j++) {
        int2 e = pk[j];
        int2 q = *(const int2*)&S[(size_t)e.x * 64 + sub4];
        GEDGE(e, q)
    }
}

// ---------------- g1 / g2: fp16-out gathers, grid.y = meta; 2 rows per warp ----------------
template<int NP>
__global__ void spmm_gather_kernel(const int* __restrict__ idxes_seq,
                                   const int* __restrict__ idxes_res) {
    int m = blockIdx.y;
    int gid = blockIdx.x * 256 + threadIdx.x;
    int w = gid >> 5;
    if (w >= NN / 2) return;                 // NN even
    int lane = threadIdx.x & 31;
    int row  = w * 2 + (lane >> 4);
    int sub4 = (lane & 15) * 4;
    const int* seq = idxes_seq + m * 3;
    const int* res = idxes_res + m * 3;

    float a0 = 0.f, a1 = 0.f, a2 = 0.f, a3 = 0.f;
    if (NP == 1) {
        gath_pass2(st_ptr(m, 0), seq[0], row, sub4, a0, a1, a2, a3);
    } else {
        gath_pass2(st_ptr(m, 1), seq[1], row, sub4, a0, a1, a2, a3);
        gath_pass2(st_ptr(m, 0), res[0], row, sub4, a0, a1, a2, a3);
    }
    __half* D = (__half*)st_ptr(m, NP);
    __half2 h01 = __floats2half2_rn(a0, a1);
    __half2 h23 = __floats2half2_rn(a2, a3);
    uint2 o;
    o.x = *reinterpret_cast<unsigned int*>(&h01);
    o.y = *reinterpret_cast<unsigned int*>(&h23);
    *(uint2*)&D[(size_t)row * 64 + sub4] = o;
}

// ---------------- single s3 pass: s3 += A[idx[m*3+off]] . s_src, red.add.v4 ----------------
__global__ void spmm_pass_kernel(const int* __restrict__ idx_arr, int off, int src_id) {
    int m = blockIdx.y;
    int gid = blockIdx.x * 256 + threadIdx.x;
    int w = gid >> 5;
    if (w >= NN / 2) return;
    int lane = threadIdx.x & 31;
    int row  = w * 2 + (lane >> 4);
    int sub4 = (lane & 15) * 4;
    int aidx = idx_arr[m * 3 + off];

    float a0 = 0.f, a1 = 0.f, a2 = 0.f, a3 = 0.f;
    gath_pass2(st_ptr(m, src_id), aidx, row, sub4, a0, a1, a2, a3);
    red_add_v4(&g_s3[m][(size_t)row * 64 + sub4], a0, a1, a2, a3);
}

// ---------------- layernorm + exact gelu + attention logit; grid.y = meta ----------------
__global__ void post_kernel(const float* __restrict__ norm_g, const float* __restrict__ norm_b,
                            const float* __restrict__ A1, const float* __restrict__ b1,
                            const float* __restrict__ a2, const float* __restrict__ b2) {
    __shared__ float A1s[64][68];
    __shared__ float hs[8][68];
    __shared__ float b1s[64];
    __shared__ float a2s[64];
    int meta = blockIdx.y;
    const float* gvec = norm_g + meta * 64;
    const float* bvec = norm_b + meta * 64;
    int t = threadIdx.x;
    for (int i = t; i < 4096; i += 256) {
        int a = i >> 6, k = i & 63;
        A1s[a][k] = A1[i];
    }
    if (t < 64) { b1s[t] = b1[t]; a2s[t] = a2[t]; }
    __syncthreads();

    int w = t >> 5;
    int lane = t & 31;
    int node = blockIdx.x * 8 + w;
    if (node >= NN) return;

    float* T = g_t[meta];
    const float* S = g_s3[meta];

    float h0 = S[(size_t)node * 64 + lane];
    float h1 = S[(size_t)node * 64 + lane + 32];
    float mu = warp_sum(h0 + h1) * (1.0f / 64.0f);
    float d0 = h0 - mu, d1 = h1 - mu;
    float var = warp_sum(d0 * d0 + d1 * d1) * (1.0f / 64.0f);
    float rstd = rsqrtf(var + 1e-5f);
    float n0 = d0 * rstd * gvec[lane] + bvec[lane];
    float n1 = d1 * rstd * gvec[lane + 32] + bvec[lane + 32];
    float ge0 = 0.5f * n0 * (1.0f + erff(n0 * 0.70710678118654752f));
    float ge1 = 0.5f * n1 * (1.0f + erff(n1 * 0.70710678118654752f));
    T[(size_t)node * 64 + lane] = ge0;
    T[(size_t)node * 64 + lane + 32] = ge1;
    hs[w][lane] = ge0;
    hs[w][lane + 32] = ge1;
    __syncwarp();

    float part = 0.f;
    #pragma unroll
    for (int half = 0; half < 2; half++) {
        int a = lane + half * 32;
        float acc = b1s[a];
        #pragma unroll
        for (int k4 = 0; k4 < 16; k4++) {
            float4 wv = *(const float4*)&A1s[a][k4 * 4];
            float4 hv = *(const float4*)&hs[w][k4 * 4];
            acc += wv.x * hv.x + wv.y * hv.y + wv.z * hv.z + wv.w * hv.w;
        }
        part += tanhf(acc) * a2s[a];
    }
    part = warp_sum(part);
    if (lane == 0) g_logits[node * 2 + meta] = part + b2[0];
}

// ---------------- 2-way softmax over metas + weighted sum -> out ----------------
__global__ void mix_kernel(float* __restrict__ out) {
    int idx = blockIdx.x * 256 + threadIdx.x;
    if (idx >= NN * 16) return;
    int node = idx >> 4, q = idx & 15;
    float l0 = g_logits[node * 2 + 0];
    float l1 = g_logits[node * 2 + 1];
    float mx = fmaxf(l0, l1);
    float e0 = expf(l0 - mx), e1 = expf(l1 - mx);
    float inv = 1.0f / (e0 + e1);
    float w0 = e0 * inv, w1 = e1 * inv;
    float4 a = *(const float4*)&g_t[0][(size_t)node * 64 + q * 4];
    float4 b = *(const float4*)&g_t[1][(size_t)node * 64 + q * 4];
    *(float4*)&out[(size_t)node * 64 + q * 4] =
        make_float4(w0 * a.x + w1 * b.x, w0 * a.y + w1 * b.y,
                    w0 * a.z + w1 * b.z, w0 * a.w + w1 * b.w);
}

extern "C" void kernel_launch(void* const* d_in, const int* in_sizes, int n_in,
                              void* d_out, int out_size) {
    const float* feats0      = (const float*)d_in[0];
    const float* feats1      = (const float*)d_in[1];
    const float* feats2      = (const float*)d_in[2];
    const float* ws_W        = (const float*)d_in[3];
    const float* ws_b        = (const float*)d_in[4];
    const float* adj_vals    = (const float*)d_in[5];
    const float* cell_aff_W  = (const float*)d_in[6];
    const float* cell_aff_b  = (const float*)d_in[7];
    const float* cell_norm_g = (const float*)d_in[8];
    const float* cell_norm_b = (const float*)d_in[9];
    const float* attn1_W     = (const float*)d_in[10];
    const float* attn1_b     = (const float*)d_in[11];
    const float* attn2_W     = (const float*)d_in[12];
    const float* attn2_b     = (const float*)d_in[13];
    // d_in[14] = node_types (contiguous blocks; unused)
    const int* adj_rows      = (const int*)d_in[15];
    const int* adj_cols      = (const int*)d_in[16];
    const int* idxes_seq     = (const int*)d_in[17];   // [2,3]
    const int* idxes_res     = (const int*)d_in[18];   // [2,3]
    float* out = (float*)d_out;

    const int S0_BLOCKS     = (NPT + 63) / 64;
    const int EDGE16_BLOCKS = (NADJ * NNZC / 16 + 255) / 256;
    const int CNT_BLOCKS    = (NADJ * NN + 255) / 256;
    const int GATH2_BLOCKS  = ((NN / 2) * 32 + 255) / 256;   // 2 rows per warp
    const int ZS3_BLOCKS    = (NN * NH * 2 / 4 + 255) / 256;
    const int POST_BLOCKS   = (NN + 7) / 8;
    const int MIX_BLOCKS    = (NN * 16 + 255) / 256;

    cudaStream_t s2;
    cudaStreamCreate(&s2);
    cudaEvent_t eFork, eA, eB, eG1, eRes;
    cudaEventCreateWithFlags(&eFork, cudaEventDisableTiming);
    cudaEventCreateWithFlags(&eA, cudaEventDisableTiming);
    cudaEventCreateWithFlags(&eB, cudaEventDisableTiming);
    cudaEventCreateWithFlags(&eG1, cudaEventDisableTiming);
    cudaEventCreateWithFlags(&eRes, cudaEventDisableTiming);
    cudaEventRecord(eFork, 0);
    cudaStreamWaitEvent(s2, eFork, 0);

    // ---- branch B (s2): weights + s0 + zero s3 ----
    wcomb_kernel<<<6, 256, 0, s2>>>(cell_aff_W, cell_aff_b, ws_W, ws_b);
    s0_kernel<<<dim3(S0_BLOCKS, 3), 256, 0, s2>>>(feats0, feats1, feats2);
    zero_s3_kernel<<<ZS3_BLOCKS, 256, 0, s2>>>();
    cudaEventRecord(eB, s2);

    // ---- branch A (default stream): CSR build ----
    zero_counts_kernel<<<CNT_BLOCKS, 256>>>();
    hist_kernel<<<EDGE16_BLOCKS, 256>>>(adj_rows);
    scanA_kernel<<<dim3(NT, NADJ), 1024>>>();
    scanB_kernel<<<NADJ, 128>>>();
    scanC_kernel<<<dim3(NT, NADJ), 1024>>>();
    scatter_kernel<<<EDGE16_BLOCKS, 256>>>(adj_rows, adj_cols, adj_vals);
    cudaEventRecord(eA, 0);

    // cross-join: stream0 needs s0+zero(eB); s2 needs CSR(eA)
    cudaStreamWaitEvent(0, eB, 0);
    cudaStreamWaitEvent(s2, eA, 0);

    // ---- stage 1: g1 (s1 = A[seq0] s0)  ||  res1 pass (s3 += A[res1] s0) ----
    spmm_gather_kernel<1><<<dim3(GATH2_BLOCKS, 2), 256>>>(idxes_seq, idxes_res);
    cudaEventRecord(eG1, 0);
    spmm_pass_kernel<<<dim3(GATH2_BLOCKS, 2), 256, 0, s2>>>(idxes_res, 1, 0);

    // ---- stage 2: g2 (s2 = A[seq1] s1 + A[res0] s0)  ||  res2 pass (s3 += A[res2] s1) ----
    spmm_gather_kernel<2><<<dim3(GATH2_BLOCKS, 2), 256>>>(idxes_seq, idxes_res);
    cudaStreamWaitEvent(s2, eG1, 0);
    spmm_pass_kernel<<<dim3(GATH2_BLOCKS, 2), 256, 0, s2>>>(idxes_res, 2, 1);
    cudaEventRecord(eRes, s2);

    // ---- stage 3: s3 += A[seq2] s2, then post + mix ----
    spmm_pass_kernel<<<dim3(GATH2_BLOCKS, 2), 256>>>(idxes_seq, 2, 2);
    cudaStreamWaitEvent(0, eRes, 0);
    post_kernel<<<dim3(POST_BLOCKS, 2), 256>>>(cell_norm_g, cell_norm_b,
                                               attn1_W, attn1_b, attn2_W, attn2_b);
    mix_kernel<<<MIX_BLOCKS, 256>>>(out);

    cudaEventDestroy(eFork);
    cudaEventDestroy(eA);
    cudaEventDestroy(eB);
    cudaEventDestroy(eG1);
    cudaEventDestroy(eRes);
    cudaStreamDestroy(s2);
}

// round 16
// speedup vs baseline: 1.6926x; 1.0559x over previous
#include <cuda_runtime.h>
#include <cuda_fp16.h>
#include <math.h>

#define NN   99000
#define NH   64
#define NNZC 1584000
#define NADJ 6
#define NPT  33000
#define NT   97          // scan tiles per adjacency: ceil(99000/1024)

// ---------------- scratch (device globals; no runtime allocation) ----------------
__device__ __half g_st[2][3][NN * NH];   // fp16 states s0,s1,s2 per meta
__device__ float  g_s3[2][NN * NH];      // fp32 final state per meta (red.add target)
__device__ float  g_t[2][NN * NH];       // gelu output per meta
__device__ float  g_logits[NN * 2];
__device__ float  g_Wc[2][3][NH * NH];   // composed weights, transposed: [k_in*64 + i_out]
__device__ float  g_bc[2][3][NH];        // composed biases

// CSR scratch
__device__ int  g_cursor[NADJ * NN];
__device__ int  g_rowptr[NADJ * (NN + 1)];
__device__ int  g_tilesum[NADJ * NT];
__device__ int  g_tileoff[NADJ * NT];
__device__ int2 g_pack[(size_t)NADJ * NNZC];  // (col, val bits) sorted by row

__device__ __forceinline__ const __half* st_ptr(int m, int id) {
    return g_st[m][id];
}

__device__ __forceinline__ float warp_sum(float v) {
    #pragma unroll
    for (int o = 16; o > 0; o >>= 1) v += __shfl_xor_sync(0xffffffffu, v, o);
    return v;
}

__device__ __forceinline__ void red_add_v4(float* p, float a, float b, float c, float d) {
    asm volatile("red.global.add.v4.f32 [%0], {%1,%2,%3,%4};"
                 :: "l"(p), "f"(a), "f"(b), "f"(c), "f"(d) : "memory");
}

// ---------------- CSR build ----------------
__global__ void zero_counts_kernel() {
    int i = blockIdx.x * 256 + threadIdx.x;
    if (i < NADJ * NN) g_cursor[i] = 0;
}

__global__ void hist_kernel(const int* __restrict__ rows) {
    int i = blockIdx.x * 256 + threadIdx.x;
    if (i >= NADJ * NNZC / 16) return;
    int a = (i * 16) / NNZC;
    int* cnt = g_cursor + a * NN;
    #pragma unroll
    for (int h = 0; h < 4; h++) {
        int4 r = *(const int4*)&rows[i * 16 + h * 4];
        atomicAdd(&cnt[r.x], 1); atomicAdd(&cnt[r.y], 1);
        atomicAdd(&cnt[r.z], 1); atomicAdd(&cnt[r.w], 1);
    }
}

__global__ void scanA_kernel() {
    __shared__ int sh[32];
    int a = blockIdx.y, tile = blockIdx.x;
    int idx = tile * 1024 + threadIdx.x;
    int lane = threadIdx.x & 31, wid = threadIdx.x >> 5;
    int v = (idx < NN) ? g_cursor[a * NN + idx] : 0;
    int s = v;
    #pragma unroll
    for (int o = 1; o < 32; o <<= 1) {
        int n = __shfl_up_sync(0xffffffffu, s, o);
        if (lane >= o) s += n;
    }
    if (lane == 31) sh[wid] = s;
    __syncthreads();
    if (wid == 0) {
        int w = sh[lane];
        #pragma unroll
        for (int o = 1; o < 32; o <<= 1) {
            int n = __shfl_up_sync(0xffffffffu, w, o);
            if (lane >= o) w += n;
        }
        sh[lane] = w;
    }
    __syncthreads();
    int incl = s + ((wid > 0) ? sh[wid - 1] : 0);
    if (idx < NN) g_rowptr[a * (NN + 1) + idx] = incl - v;
    if (threadIdx.x == 1023) g_tilesum[a * NT + tile] = incl;
}

__global__ void scanB_kernel() {
    __shared__ int sh[4];
    int a = blockIdx.x, t = threadIdx.x;
    int lane = t & 31, wid = t >> 5;
    int orig = (t < NT) ? g_tilesum[a * NT + t] : 0;
    int s = orig;
    #pragma unroll
    for (int o = 1; o < 32; o <<= 1) {
        int n = __shfl_up_sync(0xffffffffu, s, o);
        if (lane >= o) s += n;
    }
    if (lane == 31) sh[wid] = s;
    __syncthreads();
    int add = 0;
    for (int w = 0; w < wid; w++) add += sh[w];
    int incl = s + add;
    if (t < NT) g_tileoff[a * NT + t] = incl - orig;
    if (t == NT - 1) g_rowptr[a * (NN + 1) + NN] = incl;
}

__global__ void scanC_kernel() {
    int a = blockIdx.y;
    int idx = blockIdx.x * 1024 + threadIdx.x;
    if (idx >= NN) return;
    int off = g_tileoff[a * NT + blockIdx.x];
    int e = g_rowptr[a * (NN + 1) + idx] + off;
    g_rowptr[a * (NN + 1) + idx] = e;
    g_cursor[a * NN + idx] = e;
}

__global__ void scatter_kernel(const int* __restrict__ rows, const int* __restrict__ cols,
                               const float* __restrict__ vals) {
    int i = blockIdx.x * 256 + threadIdx.x;
    if (i >= NADJ * NNZC / 16) return;
    int a = (i * 16) / NNZC;
    int* cur = g_cursor + a * NN;
    int2* pk = (int2*)(g_pack + (size_t)a * NNZC);
    #pragma unroll
    for (int h = 0; h < 4; h++) {
        int base = i * 16 + h * 4;
        int4 r = *(const int4*)&rows[base];
        int4 c = *(const int4*)&cols[base];
        float4 v = *(const float4*)&vals[base];
        int p0 = atomicAdd(&cur[r.x], 1);
        int p1 = atomicAdd(&cur[r.y], 1);
        int p2 = atomicAdd(&cur[r.z], 1);
        int p3 = atomicAdd(&cur[r.w], 1);
        pk[p0] = make_int2(c.x, __float_as_int(v.x));
        pk[p1] = make_int2(c.y, __float_as_int(v.y));
        pk[p2] = make_int2(c.z, __float_as_int(v.z));
        pk[p3] = make_int2(c.w, __float_as_int(v.w));
    }
}

// ---------------- weight composition ----------------
__global__ void wcomb_kernel(const float* __restrict__ cW, const float* __restrict__ cb,
                             const float* __restrict__ wsW, const float* __restrict__ wsb) {
    __shared__ float cs[64][65];
    __shared__ float ws[64][65];
    int blk = blockIdx.x;
    int m = blk / 3;
    int t = blk % 3;
    int tid = threadIdx.x;
    for (int i = tid; i < 4096; i += 256) {
        int r = i >> 6, c = i & 63;
        cs[r][c] = cW[m * 4096 + i];
        ws[r][c] = wsW[t * 4096 + i];
    }
    __syncthreads();
    for (int e = tid; e < 4096; e += 256) {
        int i = e >> 6, k = e & 63;
        float acc = 0.f;
        #pragma unroll
        for (int q = 0; q < 64; q++) acc += cs[i][q] * ws[q][k];
        g_Wc[m][t][k * 64 + i] = acc;
    }
    if (tid < 64) {
        float acc = cb[m * 64 + tid];
        #pragma unroll
        for (int q = 0; q < 64; q++) acc += cs[tid][q] * wsb[t * 64 + q];
        g_bc[m][t][tid] = acc;
    }
}

// ---------------- fused s0: both metas from feats directly ----------------
__global__ void s0_kernel(const float* __restrict__ f0, const float* __restrict__ f1,
                          const float* __restrict__ f2) {
    __shared__ float Xs[64][68];
    __shared__ float Wt[64][64];
    __shared__ float bs[64];
    int type = blockIdx.y;
    const float* X = (type == 0) ? f0 : (type == 1) ? f1 : f2;
    int t = threadIdx.x;
    int lrow0 = blockIdx.x * 64;
    for (int i = t; i < 1024; i += 256) {
        int r = i >> 4, q = i & 15;
        float4 v = make_float4(0.f, 0.f, 0.f, 0.f);
        if (lrow0 + r < NPT) v = *(const float4*)&X[(size_t)(lrow0 + r) * 64 + q * 4];
        *(float4*)&Xs[r][q * 4] = v;
    }
    int nd = t >> 3;
    int cg = (t & 7) * 8;
    #pragma unroll
    for (int m = 0; m < 2; m++) {
        __syncthreads();
        for (int i = t; i < 4096; i += 256) ((float*)Wt)[i] = g_Wc[m][type][i];
        if (t < 64) bs[t] = g_bc[m][type][t];
        __syncthreads();
        float acc0[8], acc1[8];
        #pragma unroll
        for (int j = 0; j < 8; j++) { acc0[j] = bs[cg + j]; acc1[j] = bs[cg + j]; }
        #pragma unroll
        for (int k = 0; k < 64; k++) {
            float x0 = Xs[nd][k];
            float x1 = Xs[nd + 32][k];
            float4 w0 = *(const float4*)&Wt[k][cg];
            float4 w1 = *(const float4*)&Wt[k][cg + 4];
            acc0[0] += x0 * w0.x; acc0[1] += x0 * w0.y; acc0[2] += x0 * w0.z; acc0[3] += x0 * w0.w;
            acc0[4] += x0 * w1.x; acc0[5] += x0 * w1.y; acc0[6] += x0 * w1.z; acc0[7] += x0 * w1.w;
            acc1[0] += x1 * w0.x; acc1[1] += x1 * w0.y; acc1[2] += x1 * w0.z; acc1[3] += x1 * w0.w;
            acc1[4] += x1 * w1.x; acc1[5] += x1 * w1.y; acc1[6] += x1 * w1.z; acc1[7] += x1 * w1.w;
        }
        __half* D = (__half*)g_st[m][0];
        int r0 = type * NPT + lrow0 + nd;
        int r1 = r0 + 32;
        if (lrow0 + nd < NPT) {
            __half2* yp = (__half2*)&D[(size_t)r0 * 64 + cg];
            yp[0] = __floats2half2_rn(acc0[0], acc0[1]);
            yp[1] = __floats2half2_rn(acc0[2], acc0[3]);
            yp[2] = __floats2half2_rn(acc0[4], acc0[5]);
            yp[3] = __floats2half2_rn(acc0[6], acc0[7]);
        }
        if (lrow0 + nd + 32 < NPT) {
            __half2* yp = (__half2*)&D[(size_t)r1 * 64 + cg];
            yp[0] = __floats2half2_rn(acc1[0], acc1[1]);
            yp[1] = __floats2half2_rn(acc1[2], acc1[3]);
            yp[2] = __floats2half2_rn(acc1[4], acc1[5]);
            yp[3] = __floats2half2_rn(acc1[6], acc1[7]);
        }
    }
}

// ---------------- zero s3 (both metas) ----------------
__global__ void zero_s3_kernel() {
    int i = blockIdx.x * 256 + threadIdx.x;
    if (i < NN * NH * 2 / 4) ((float4*)g_s3)[i] = make_float4(0.f, 0.f, 0.f, 0.f);
}

// ---------------- gather core: quarter-warp per row, 8 halves (int4) per lane ----------------
// sub8 = (lane & 7) * 8 : this lane owns columns [sub8, sub8+8)
#define GEDGE8(e, q)                                                    \
    {                                                                   \
        float v = __int_as_float((e).y);                                \
        float2 p0 = __half22float2(*(const __half2*)&(q).x);            \
        float2 p1 = __half22float2(*(const __half2*)&(q).y);            \
        float2 p2 = __half22float2(*(const __half2*)&(q).z);            \
        float2 p3 = __half22float2(*(const __half2*)&(q).w);            \
        a0 += v * p0.x; a1 += v * p0.y; a2 += v * p1.x; a3 += v * p1.y; \
        a4 += v * p2.x; a5 += v * p2.y; a6 += v * p3.x; a7 += v * p3.y; \
    }

__device__ __forceinline__ void gath_pass4(const __half* __restrict__ S, int aidx,
                                           int row, int sub8,
                                           float& a0, float& a1, float& a2, float& a3,
                                           float& a4, float& a5, float& a6, float& a7) {
    const int* rp = g_rowptr + aidx * (NN + 1);
    int j   = rp[row];
    int end = rp[row + 1];
    const int2* __restrict__ pk = g_pack + (size_t)aidx * NNZC;

    for (; j + 4 <= end; j += 4) {
        int2 e0 = pk[j], e1 = pk[j + 1], e2 = pk[j + 2], e3 = pk[j + 3];
        int4 q0 = *(const int4*)&S[(size_t)e0.x * 64 + sub8];
        int4 q1 = *(const int4*)&S[(size_t)e1.x * 64 + sub8];
        int4 q2 = *(const int4*)&S[(size_t)e2.x * 64 + sub8];
        int4 q3 = *(const int4*)&S[(size_t)e3.x * 64 + sub8];
        GEDGE8(e0, q0) GEDGE8(e1, q1) GEDGE8(e2, q2) GEDGE8(e3, q3)
    }
    for (; j < end; j++) {
        int2 e = pk[j];
        int4 q = *(const int4*)&S[(size_t)e.x * 64 + sub8];
        GEDGE8(e, q)
    }
}

// ---------------- g1 / g2: fp16-out gathers, grid.y = meta; 4 rows per warp ----------------
template<int NP>
__global__ void spmm_gather_kernel(const int* __restrict__ idxes_seq,
                                   const int* __restrict__ idxes_res) {
    int m = blockIdx.y;
    int gid = blockIdx.x * 256 + threadIdx.x;
    int w = gid >> 5;
    if (w >= NN / 4) return;                 // NN % 4 == 0
    int lane = threadIdx.x & 31;
    int row  = w * 4 + (lane >> 3);
    int sub8 = (lane & 7) * 8;
    const int* seq = idxes_seq + m * 3;
    const int* res = idxes_res + m * 3;

    float a0 = 0.f, a1 = 0.f, a2 = 0.f, a3 = 0.f;
    float a4 = 0.f, a5 = 0.f, a6 = 0.f, a7 = 0.f;
    if (NP == 1) {
        gath_pass4(st_ptr(m, 0), seq[0], row, sub8, a0, a1, a2, a3, a4, a5, a6, a7);
    } else {
        gath_pass4(st_ptr(m, 1), seq[1], row, sub8, a0, a1, a2, a3, a4, a5, a6, a7);
        gath_pass4(st_ptr(m, 0), res[0], row, sub8, a0, a1, a2, a3, a4, a5, a6, a7);
    }
    __half* D = (__half*)st_ptr(m, NP);
    __half2 h0 = __floats2half2_rn(a0, a1);
    __half2 h1 = __floats2half2_rn(a2, a3);
    __half2 h2 = __floats2half2_rn(a4, a5);
    __half2 h3 = __floats2half2_rn(a6, a7);
    uint4 o;
    o.x = *reinterpret_cast<unsigned int*>(&h0);
    o.y = *reinterpret_cast<unsigned int*>(&h1);
    o.z = *reinterpret_cast<unsigned int*>(&h2);
    o.w = *reinterpret_cast<unsigned int*>(&h3);
    *(uint4*)&D[(size_t)row * 64 + sub8] = o;
}

// ---------------- single s3 pass: s3 += A[idx[m*3+off]] . s_src, 2x red.add.v4 ----------------
__global__ void spmm_pass_kernel(const int* __restrict__ idx_arr, int off, int src_id) {
    int m = blockIdx.y;
    int gid = blockIdx.x * 256 + threadIdx.x;
    int w = gid >> 5;
    if (w >= NN / 4) return;
    int lane = threadIdx.x & 31;
    int row  = w * 4 + (lane >> 3);
    int sub8 = (lane & 7) * 8;
    int aidx = idx_arr[m * 3 + off];

    float a0 = 0.f, a1 = 0.f, a2 = 0.f, a3 = 0.f;
    float a4 = 0.f, a5 = 0.f, a6 = 0.f, a7 = 0.f;
    gath_pass4(st_ptr(m, src_id), aidx, row, sub8, a0, a1, a2, a3, a4, a5, a6, a7);
    float* base = &g_s3[m][(size_t)row * 64 + sub8];
    red_add_v4(base,     a0, a1, a2, a3);
    red_add_v4(base + 4, a4, a5, a6, a7);
}

// ---------------- layernorm + exact gelu + attention logit; grid.y = meta ----------------
__global__ void post_kernel(const float* __restrict__ norm_g, const float* __restrict__ norm_b,
                            const float* __restrict__ A1, const float* __restrict__ b1,
                            const float* __restrict__ a2, const float* __restrict__ b2) {
    __shared__ float A1s[64][68];
    __shared__ float hs[8][68];
    __shared__ float b1s[64];
    __shared__ float a2s[64];
    int meta = blockIdx.y;
    const float* gvec = norm_g + meta * 64;
    const float* bvec = norm_b + meta * 64;
    int t = threadIdx.x;
    for (int i = t; i < 4096; i += 256) {
        int a = i >> 6, k = i & 63;
        A1s[a][k] = A1[i];
    }
    if (t < 64) { b1s[t] = b1[t]; a2s[t] = a2[t]; }
    __syncthreads();

    int w = t >> 5;
    int lane = t & 31;
    int node = blockIdx.x * 8 + w;
    if (node >= NN) return;

    float* T = g_t[meta];
    const float* S = g_s3[meta];

    float h0 = S[(size_t)node * 64 + lane];
    float h1 = S[(size_t)node * 64 + lane + 32];
    float mu = warp_sum(h0 + h1) * (1.0f / 64.0f);
    float d0 = h0 - mu, d1 = h1 - mu;
    float var = warp_sum(d0 * d0 + d1 * d1) * (1.0f / 64.0f);
    float rstd = rsqrtf(var + 1e-5f);
    float n0 = d0 * rstd * gvec[lane] + bvec[lane];
    float n1 = d1 * rstd * gvec[lane + 32] + bvec[lane + 32];
    float ge0 = 0.5f * n0 * (1.0f + erff(n0 * 0.70710678118654752f));
    float ge1 = 0.5f * n1 * (1.0f + erff(n1 * 0.70710678118654752f));
    T[(size_t)node * 64 + lane] = ge0;
    T[(size_t)node * 64 + lane + 32] = ge1;
    hs[w][lane] = ge0;
    hs[w][lane + 32] = ge1;
    __syncwarp();

    float part = 0.f;
    #pragma unroll
    for (int half = 0; half < 2; half++) {
        int a = lane + half * 32;
        float acc = b1s[a];
        #pragma unroll
        for (int k4 = 0; k4 < 16; k4++) {
            float4 wv = *(const float4*)&A1s[a][k4 * 4];
            float4 hv = *(const float4*)&hs[w][k4 * 4];
            acc += wv.x * hv.x + wv.y * hv.y + wv.z * hv.z + wv.w * hv.w;
        }
        part += tanhf(acc) * a2s[a];
    }
    part = warp_sum(part);
    if (lane == 0) g_logits[node * 2 + meta] = part + b2[0];
}

// ---------------- 2-way softmax over metas + weighted sum -> out ----------------
__global__ void mix_kernel(float* __restrict__ out) {
    int idx = blockIdx.x * 256 + threadIdx.x;
    if (idx >= NN * 16) return;
    int node = idx >> 4, q = idx & 15;
    float l0 = g_logits[node * 2 + 0];
    float l1 = g_logits[node * 2 + 1];
    float mx = fmaxf(l0, l1);
    float e0 = expf(l0 - mx), e1 = expf(l1 - mx);
    float inv = 1.0f / (e0 + e1);
    float w0 = e0 * inv, w1 = e1 * inv;
    float4 a = *(const float4*)&g_t[0][(size_t)node * 64 + q * 4];
    float4 b = *(const float4*)&g_t[1][(size_t)node * 64 + q * 4];
    *(float4*)&out[(size_t)node * 64 + q * 4] =
        make_float4(w0 * a.x + w1 * b.x, w0 * a.y + w1 * b.y,
                    w0 * a.z + w1 * b.z, w0 * a.w + w1 * b.w);
}

extern "C" void kernel_launch(void* const* d_in, const int* in_sizes, int n_in,
                              void* d_out, int out_size) {
    const float* feats0      = (const float*)d_in[0];
    const float* feats1      = (const float*)d_in[1];
    const float* feats2      = (const float*)d_in[2];
    const float* ws_W        = (const float*)d_in[3];
    const float* ws_b        = (const float*)d_in[4];
    const float* adj_vals    = (const float*)d_in[5];
    const float* cell_aff_W  = (const float*)d_in[6];
    const float* cell_aff_b  = (const float*)d_in[7];
    const float* cell_norm_g = (const float*)d_in[8];
    const float* cell_norm_b = (const float*)d_in[9];
    const float* attn1_W     = (const float*)d_in[10];
    const float* attn1_b     = (const float*)d_in[11];
    const float* attn2_W     = (const float*)d_in[12];
    const float* attn2_b     = (const float*)d_in[13];
    // d_in[14] = node_types (contiguous blocks; unused)
    const int* adj_rows      = (const int*)d_in[15];
    const int* adj_cols      = (const int*)d_in[16];
    const int* idxes_seq     = (const int*)d_in[17];   // [2,3]
    const int* idxes_res     = (const int*)d_in[18];   // [2,3]
    float* out = (float*)d_out;

    const int S0_BLOCKS     = (NPT + 63) / 64;
    const int EDGE16_BLOCKS = (NADJ * NNZC / 16 + 255) / 256;
    const int CNT_BLOCKS    = (NADJ * NN + 255) / 256;
    const int GATH4_BLOCKS  = ((NN / 4) * 32 + 255) / 256;   // 4 rows per warp
    const int ZS3_BLOCKS    = (NN * NH * 2 / 4 + 255) / 256;
    const int POST_BLOCKS   = (NN + 7) / 8;
    const int MIX_BLOCKS    = (NN * 16 + 255) / 256;

    cudaStream_t s2;
    cudaStreamCreate(&s2);
    cudaEvent_t eFork, eA, eB, eG1, eRes;
    cudaEventCreateWithFlags(&eFork, cudaEventDisableTiming);
    cudaEventCreateWithFlags(&eA, cudaEventDisableTiming);
    cudaEventCreateWithFlags(&eB, cudaEventDisableTiming);
    cudaEventCreateWithFlags(&eG1, cudaEventDisableTiming);
    cudaEventCreateWithFlags(&eRes, cudaEventDisableTiming);
    cudaEventRecord(eFork, 0);
    cudaStreamWaitEvent(s2, eFork, 0);

    // ---- branch B (s2): weights + s0 + zero s3 ----
    wcomb_kernel<<<6, 256, 0, s2>>>(cell_aff_W, cell_aff_b, ws_W, ws_b);
    s0_kernel<<<dim3(S0_BLOCKS, 3), 256, 0, s2>>>(feats0, feats1, feats2);
    zero_s3_kernel<<<ZS3_BLOCKS, 256, 0, s2>>>();
    cudaEventRecord(eB, s2);

    // ---- branch A (default stream): CSR build ----
    zero_counts_kernel<<<CNT_BLOCKS, 256>>>();
    hist_kernel<<<EDGE16_BLOCKS, 256>>>(adj_rows);
    scanA_kernel<<<dim3(NT, NADJ), 1024>>>();
    scanB_kernel<<<NADJ, 128>>>();
    scanC_kernel<<<dim3(NT, NADJ), 1024>>>();
    scatter_kernel<<<EDGE16_BLOCKS, 256>>>(adj_rows, adj_cols, adj_vals);
    cudaEventRecord(eA, 0);

    // cross-join: stream0 needs s0+zero(eB); s2 needs CSR(eA)
    cudaStreamWaitEvent(0, eB, 0);
    cudaStreamWaitEvent(s2, eA, 0);

    // ---- stage 1: g1 (s1 = A[seq0] s0)  ||  res1 pass (s3 += A[res1] s0) ----
    spmm_gather_kernel<1><<<dim3(GATH4_BLOCKS, 2), 256>>>(idxes_seq, idxes_res);
    cudaEventRecord(eG1, 0);
    spmm_pass_kernel<<<dim3(GATH4_BLOCKS, 2), 256, 0, s2>>>(idxes_res, 1, 0);

    // ---- stage 2: g2 (s2 = A[seq1] s1 + A[res0] s0)  ||  res2 pass (s3 += A[res2] s1) ----
    spmm_gather_kernel<2><<<dim3(GATH4_BLOCKS, 2), 256>>>(idxes_seq, idxes_res);
    cudaStreamWaitEvent(s2, eG1, 0);
    spmm_pass_kernel<<<dim3(GATH4_BLOCKS, 2), 256, 0, s2>>>(idxes_res, 2, 1);
    cudaEventRecord(eRes, s2);

    // ---- stage 3: s3 += A[seq2] s2, then post + mix ----
    spmm_pass_kernel<<<dim3(GATH4_BLOCKS, 2), 256>>>(idxes_seq, 2, 2);
    cudaStreamWaitEvent(0, eRes, 0);
    post_kernel<<<dim3(POST_BLOCKS, 2), 256>>>(cell_norm_g, cell_norm_b,
                                               attn1_W, attn1_b, attn2_W, attn2_b);
    mix_kernel<<<MIX_BLOCKS, 256>>>(out);

    cudaEventDestroy(eFork);
    cudaEventDestroy(eA);
    cudaEventDestroy(eB);
    cudaEventDestroy(eG1);
    cudaEventDestroy(eRes);
    cudaStreamDestroy(s2);
}

// round 17
// speedup vs baseline: 1.7012x; 1.0051x over previous
#include <cuda_runtime.h>
#include <cuda_fp16.h>
#include <math.h>

#define NN   99000
#define NH   64
#define NNZC 1584000
#define NADJ 6
#define NPT  33000
#define NT   97          // scan tiles per adjacency: ceil(99000/1024)

// ---------------- scratch (device globals; no runtime allocation) ----------------
__device__ __half g_st[2][3][NN * NH];   // fp16 states s0,s1,s2 per meta
__device__ float  g_s3[2][NN * NH];      // fp32 final state per meta (red.add target)
__device__ float  g_Wc[2][3][NH * NH];   // composed weights, transposed: [k_in*64 + i_out]
__device__ float  g_bc[2][3][NH];        // composed biases

// CSR scratch
__device__ int  g_cursor[NADJ * NN];
__device__ int  g_rowptr[NADJ * (NN + 1)];
__device__ int  g_tilesum[NADJ * NT];
__device__ int  g_tileoff[NADJ * NT];
__device__ int  g_rank[(size_t)NADJ * NNZC];  // per-edge rank within its row
__device__ int2 g_pack[(size_t)NADJ * NNZC];  // (col, val bits) sorted by row

__device__ __forceinline__ const __half* st_ptr(int m, int id) {
    return g_st[m][id];
}

__device__ __forceinline__ float warp_sum(float v) {
    #pragma unroll
    for (int o = 16; o > 0; o >>= 1) v += __shfl_xor_sync(0xffffffffu, v, o);
    return v;
}

__device__ __forceinline__ void red_add_v4(float* p, float a, float b, float c, float d) {
    asm volatile("red.global.add.v4.f32 [%0], {%1,%2,%3,%4};"
                 :: "l"(p), "f"(a), "f"(b), "f"(c), "f"(d) : "memory");
}

// ---------------- CSR build ----------------
__global__ void zero_counts_kernel() {
    int i = blockIdx.x * 256 + threadIdx.x;
    if (i < NADJ * NN) g_cursor[i] = 0;
}

// hist + rank capture: atomicAdd's return value is the edge's rank within its row
__global__ void hist_kernel(const int* __restrict__ rows) {
    int i = blockIdx.x * 256 + threadIdx.x;
    if (i >= NADJ * NNZC / 16) return;
    int a = (i * 16) / NNZC;
    int* cnt = g_cursor + a * NN;
    #pragma unroll
    for (int h = 0; h < 4; h++) {
        int base = i * 16 + h * 4;
        int4 r = *(const int4*)&rows[base];
        int4 k;
        k.x = atomicAdd(&cnt[r.x], 1);
        k.y = atomicAdd(&cnt[r.y], 1);
        k.z = atomicAdd(&cnt[r.z], 1);
        k.w = atomicAdd(&cnt[r.w], 1);
        *(int4*)&g_rank[base] = k;
    }
}

__global__ void scanA_kernel() {
    __shared__ int sh[32];
    int a = blockIdx.y, tile = blockIdx.x;
    int idx = tile * 1024 + threadIdx.x;
    int lane = threadIdx.x & 31, wid = threadIdx.x >> 5;
    int v = (idx < NN) ? g_cursor[a * NN + idx] : 0;
    int s = v;
    #pragma unroll
    for (int o = 1; o < 32; o <<= 1) {
        int n = __shfl_up_sync(0xffffffffu, s, o);
        if (lane >= o) s += n;
    }
    if (lane == 31) sh[wid] = s;
    __syncthreads();
    if (wid == 0) {
        int w = sh[lane];
        #pragma unroll
        for (int o = 1; o < 32; o <<= 1) {
            int n = __shfl_up_sync(0xffffffffu, w, o);
            if (lane >= o) w += n;
        }
        sh[lane] = w;
    }
    __syncthreads();
    int incl = s + ((wid > 0) ? sh[wid - 1] : 0);
    if (idx < NN) g_rowptr[a * (NN + 1) + idx] = incl - v;
    if (threadIdx.x == 1023) g_tilesum[a * NT + tile] = incl;
}

__global__ void scanB_kernel() {
    __shared__ int sh[4];
    int a = blockIdx.x, t = threadIdx.x;
    int lane = t & 31, wid = t >> 5;
    int orig = (t < NT) ? g_tilesum[a * NT + t] : 0;
    int s = orig;
    #pragma unroll
    for (int o = 1; o < 32; o <<= 1) {
        int n = __shfl_up_sync(0xffffffffu, s, o);
        if (lane >= o) s += n;
    }
    if (lane == 31) sh[wid] = s;
    __syncthreads();
    int add = 0;
    for (int w = 0; w < wid; w++) add += sh[w];
    int incl = s + add;
    if (t < NT) g_tileoff[a * NT + t] = incl - orig;
    if (t == NT - 1) g_rowptr[a * (NN + 1) + NN] = incl;
}

__global__ void scanC_kernel() {
    int a = blockIdx.y;
    int idx = blockIdx.x * 1024 + threadIdx.x;
    if (idx >= NN) return;
    int off = g_tileoff[a * NT + blockIdx.x];
    g_rowptr[a * (NN + 1) + idx] += off;
}

// atomic-free scatter: pos = rowptr[row] + rank[edge]
__global__ void scatter_kernel(const int* __restrict__ rows, const int* __restrict__ cols,
                               const float* __restrict__ vals) {
    int i = blockIdx.x * 256 + threadIdx.x;
    if (i >= NADJ * NNZC / 16) return;
    int a = (i * 16) / NNZC;
    const int* rp = g_rowptr + a * (NN + 1);
    int2* pk = (int2*)(g_pack + (size_t)a * NNZC);
    #pragma unroll
    for (int h = 0; h < 4; h++) {
        int base = i * 16 + h * 4;
        int4 r = *(const int4*)&rows[base];
        int4 c = *(const int4*)&cols[base];
        float4 v = *(const float4*)&vals[base];
        int4 k = *(const int4*)&g_rank[base];
        pk[rp[r.x] + k.x] = make_int2(c.x, __float_as_int(v.x));
        pk[rp[r.y] + k.y] = make_int2(c.y, __float_as_int(v.y));
        pk[rp[r.z] + k.z] = make_int2(c.z, __float_as_int(v.z));
        pk[rp[r.w] + k.w] = make_int2(c.w, __float_as_int(v.w));
    }
}

// ---------------- weight composition ----------------
__global__ void wcomb_kernel(const float* __restrict__ cW, const float* __restrict__ cb,
                             const float* __restrict__ wsW, const float* __restrict__ wsb) {
    __shared__ float cs[64][65];
    __shared__ float ws[64][65];
    int blk = blockIdx.x;
    int m = blk / 3;
    int t = blk % 3;
    int tid = threadIdx.x;
    for (int i = tid; i < 4096; i += 256) {
        int r = i >> 6, c = i & 63;
        cs[r][c] = cW[m * 4096 + i];
        ws[r][c] = wsW[t * 4096 + i];
    }
    __syncthreads();
    for (int e = tid; e < 4096; e += 256) {
        int i = e >> 6, k = e & 63;
        float acc = 0.f;
        #pragma unroll
        for (int q = 0; q < 64; q++) acc += cs[i][q] * ws[q][k];
        g_Wc[m][t][k * 64 + i] = acc;
    }
    if (tid < 64) {
        float acc = cb[m * 64 + tid];
        #pragma unroll
        for (int q = 0; q < 64; q++) acc += cs[tid][q] * wsb[t * 64 + q];
        g_bc[m][t][tid] = acc;
    }
}

// ---------------- fused s0: both metas from feats directly ----------------
__global__ void s0_kernel(const float* __restrict__ f0, const float* __restrict__ f1,
                          const float* __restrict__ f2) {
    __shared__ float Xs[64][68];
    __shared__ float Wt[64][64];
    __shared__ float bs[64];
    int type = blockIdx.y;
    const float* X = (type == 0) ? f0 : (type == 1) ? f1 : f2;
    int t = threadIdx.x;
    int lrow0 = blockIdx.x * 64;
    for (int i = t; i < 1024; i += 256) {
        int r = i >> 4, q = i & 15;
        float4 v = make_float4(0.f, 0.f, 0.f, 0.f);
        if (lrow0 + r < NPT) v = *(const float4*)&X[(size_t)(lrow0 + r) * 64 + q * 4];
        *(float4*)&Xs[r][q * 4] = v;
    }
    int nd = t >> 3;
    int cg = (t & 7) * 8;
    #pragma unroll
    for (int m = 0; m < 2; m++) {
        __syncthreads();
        for (int i = t; i < 4096; i += 256) ((float*)Wt)[i] = g_Wc[m][type][i];
        if (t < 64) bs[t] = g_bc[m][type][t];
        __syncthreads();
        float acc0[8], acc1[8];
        #pragma unroll
        for (int j = 0; j < 8; j++) { acc0[j] = bs[cg + j]; acc1[j] = bs[cg + j]; }
        #pragma unroll
        for (int k = 0; k < 64; k++) {
            float x0 = Xs[nd][k];
            float x1 = Xs[nd + 32][k];
            float4 w0 = *(const float4*)&Wt[k][cg];
            float4 w1 = *(const float4*)&Wt[k][cg + 4];
            acc0[0] += x0 * w0.x; acc0[1] += x0 * w0.y; acc0[2] += x0 * w0.z; acc0[3] += x0 * w0.w;
            acc0[4] += x0 * w1.x; acc0[5] += x0 * w1.y; acc0[6] += x0 * w1.z; acc0[7] += x0 * w1.w;
            acc1[0] += x1 * w0.x; acc1[1] += x1 * w0.y; acc1[2] += x1 * w0.z; acc1[3] += x1 * w0.w;
            acc1[4] += x1 * w1.x; acc1[5] += x1 * w1.y; acc1[6] += x1 * w1.z; acc1[7] += x1 * w1.w;
        }
        __half* D = (__half*)g_st[m][0];
        int r0 = type * NPT + lrow0 + nd;
        int r1 = r0 + 32;
        if (lrow0 + nd < NPT) {
            __half2* yp = (__half2*)&D[(size_t)r0 * 64 + cg];
            yp[0] = __floats2half2_rn(acc0[0], acc0[1]);
            yp[1] = __floats2half2_rn(acc0[2], acc0[3]);
            yp[2] = __floats2half2_rn(acc0[4], acc0[5]);
            yp[3] = __floats2half2_rn(acc0[6], acc0[7]);
        }
        if (lrow0 + nd + 32 < NPT) {
            __half2* yp = (__half2*)&D[(size_t)r1 * 64 + cg];
            yp[0] = __floats2half2_rn(acc1[0], acc1[1]);
            yp[1] = __floats2half2_rn(acc1[2], acc1[3]);
            yp[2] = __floats2half2_rn(acc1[4], acc1[5]);
            yp[3] = __floats2half2_rn(acc1[6], acc1[7]);
        }
    }
}

// ---------------- zero s3 (both metas) ----------------
__global__ void zero_s3_kernel() {
    int i = blockIdx.x * 256 + threadIdx.x;
    if (i < NN * NH * 2 / 4) ((float4*)g_s3)[i] = make_float4(0.f, 0.f, 0.f, 0.f);
}

// ---------------- gather core: quarter-warp per row, 8 halves (int4) per lane ----------------
#define GEDGE8(e, q)                                                    \
    {                                                                   \
        float v = __int_as_float((e).y);                                \
        float2 p0 = __half22float2(*(const __half2*)&(q).x);            \
        float2 p1 = __half22float2(*(const __half2*)&(q).y);            \
        float2 p2 = __half22float2(*(const __half2*)&(q).z);            \
        float2 p3 = __half22float2(*(const __half2*)&(q).w);            \
        a0 += v * p0.x; a1 += v * p0.y; a2 += v * p1.x; a3 += v * p1.y; \
        a4 += v * p2.x; a5 += v * p2.y; a6 += v * p3.x; a7 += v * p3.y; \
    }

__device__ __forceinline__ void gath_pass4(const __half* __restrict__ S, int aidx,
                                           int row, int sub8,
                                           float& a0, float& a1, float& a2, float& a3,
                                           float& a4, float& a5, float& a6, float& a7) {
    const int* rp = g_rowptr + aidx * (NN + 1);
    int j   = rp[row];
    int end = rp[row + 1];
    const int2* __restrict__ pk = g_pack + (size_t)aidx * NNZC;

    for (; j + 4 <= end; j += 4) {
        int2 e0 = pk[j], e1 = pk[j + 1], e2 = pk[j + 2], e3 = pk[j + 3];
        int4 q0 = *(const int4*)&S[(size_t)e0.x * 64 + sub8];
        int4 q1 = *(const int4*)&S[(size_t)e1.x * 64 + sub8];
        int4 q2 = *(const int4*)&S[(size_t)e2.x * 64 + sub8];
        int4 q3 = *(const int4*)&S[(size_t)e3.x * 64 + sub8];
        GEDGE8(e0, q0) GEDGE8(e1, q1) GEDGE8(e2, q2) GEDGE8(e3, q3)
    }
    for (; j < end; j++) {
        int2 e = pk[j];
        int4 q = *(const int4*)&S[(size_t)e.x * 64 + sub8];
        GEDGE8(e, q)
    }
}

// ---------------- g1 / g2: fp16-out gathers, grid.y = meta; 4 rows per warp ----------------
template<int NP>
__global__ void spmm_gather_kernel(const int* __restrict__ idxes_seq,
                                   const int* __restrict__ idxes_res) {
    int m = blockIdx.y;
    int gid = blockIdx.x * 256 + threadIdx.x;
    int w = gid >> 5;
    if (w >= NN / 4) return;                 // NN % 4 == 0
    int lane = threadIdx.x & 31;
    int row  = w * 4 + (lane >> 3);
    int sub8 = (lane & 7) * 8;
    const int* seq = idxes_seq + m * 3;
    const int* res = idxes_res + m * 3;

    float a0 = 0.f, a1 = 0.f, a2 = 0.f, a3 = 0.f;
    float a4 = 0.f, a5 = 0.f, a6 = 0.f, a7 = 0.f;
    if (NP == 1) {
        gath_pass4(st_ptr(m, 0), seq[0], row, sub8, a0, a1, a2, a3, a4, a5, a6, a7);
    } else {
        gath_pass4(st_ptr(m, 1), seq[1], row, sub8, a0, a1, a2, a3, a4, a5, a6, a7);
        gath_pass4(st_ptr(m, 0), res[0], row, sub8, a0, a1, a2, a3, a4, a5, a6, a7);
    }
    __half* D = (__half*)st_ptr(m, NP);
    __half2 h0 = __floats2half2_rn(a0, a1);
    __half2 h1 = __floats2half2_rn(a2, a3);
    __half2 h2 = __floats2half2_rn(a4, a5);
    __half2 h3 = __floats2half2_rn(a6, a7);
    uint4 o;
    o.x = *reinterpret_cast<unsigned int*>(&h0);
    o.y = *reinterpret_cast<unsigned int*>(&h1);
    o.z = *reinterpret_cast<unsigned int*>(&h2);
    o.w = *reinterpret_cast<unsigned int*>(&h3);
    *(uint4*)&D[(size_t)row * 64 + sub8] = o;
}

// ---------------- single s3 pass: s3 += A[idx[m*3+off]] . s_src, 2x red.add.v4 ----------------
__global__ void spmm_pass_kernel(const int* __restrict__ idx_arr, int off, int src_id) {
    int m = blockIdx.y;
    int gid = blockIdx.x * 256 + threadIdx.x;
    int w = gid >> 5;
    if (w >= NN / 4) return;
    int lane = threadIdx.x & 31;
    int row  = w * 4 + (lane >> 3);
    int sub8 = (lane & 7) * 8;
    int aidx = idx_arr[m * 3 + off];

    float a0 = 0.f, a1 = 0.f, a2 = 0.f, a3 = 0.f;
    float a4 = 0.f, a5 = 0.f, a6 = 0.f, a7 = 0.f;
    gath_pass4(st_ptr(m, src_id), aidx, row, sub8, a0, a1, a2, a3, a4, a5, a6, a7);
    float* base = &g_s3[m][(size_t)row * 64 + sub8];
    red_add_v4(base,     a0, a1, a2, a3);
    red_add_v4(base + 4, a4, a5, a6, a7);
}

// ---------------- fused epilogue: both metas' layernorm+gelu+logit + softmax mix -> out ----------------
__global__ void postmix_kernel(const float* __restrict__ norm_g, const float* __restrict__ norm_b,
                               const float* __restrict__ A1, const float* __restrict__ b1,
                               const float* __restrict__ a2, const float* __restrict__ b2,
                               float* __restrict__ out) {
    __shared__ float A1s[64][68];
    __shared__ float hs[8][2][68];
    __shared__ float b1s[64];
    __shared__ float a2s[64];
    int t = threadIdx.x;
    for (int i = t; i < 4096; i += 256) {
        int a = i >> 6, k = i & 63;
        A1s[a][k] = A1[i];
    }
    if (t < 64) { b1s[t] = b1[t]; a2s[t] = a2[t]; }
    __syncthreads();

    int w = t >> 5;
    int lane = t & 31;
    int node = blockIdx.x * 8 + w;
    if (node >= NN) return;

    float ge[2][2];
    float logit[2];
    #pragma unroll
    for (int meta = 0; meta < 2; meta++) {
        const float* S = g_s3[meta];
        float h0 = S[(size_t)node * 64 + lane];
        float h1 = S[(size_t)node * 64 + lane + 32];
        float mu = warp_sum(h0 + h1) * (1.0f / 64.0f);
        float d0 = h0 - mu, d1 = h1 - mu;
        float var = warp_sum(d0 * d0 + d1 * d1) * (1.0f / 64.0f);
        float rstd = rsqrtf(var + 1e-5f);
        float n0 = d0 * rstd * norm_g[meta * 64 + lane]      + norm_b[meta * 64 + lane];
        float n1 = d1 * rstd * norm_g[meta * 64 + lane + 32] + norm_b[meta * 64 + lane + 32];
        float ge0 = 0.5f * n0 * (1.0f + erff(n0 * 0.70710678118654752f));
        float ge1 = 0.5f * n1 * (1.0f + erff(n1 * 0.70710678118654752f));
        ge[meta][0] = ge0;
        ge[meta][1] = ge1;
        hs[w][meta][lane] = ge0;
        hs[w][meta][lane + 32] = ge1;
        __syncwarp();

        float part = 0.f;
        #pragma unroll
        for (int half = 0; half < 2; half++) {
            int a = lane + half * 32;
            float acc = b1s[a];
            #pragma unroll
            for (int k4 = 0; k4 < 16; k4++) {
                float4 wv = *(const float4*)&A1s[a][k4 * 4];
                float4 hv = *(const float4*)&hs[w][meta][k4 * 4];
                acc += wv.x * hv.x + wv.y * hv.y + wv.z * hv.z + wv.w * hv.w;
            }
            part += tanhf(acc) * a2s[a];
        }
        logit[meta] = warp_sum(part) + b2[0];   // warp_sum broadcasts to all lanes
    }

    float mx = fmaxf(logit[0], logit[1]);
    float e0 = expf(logit[0] - mx), e1 = expf(logit[1] - mx);
    float inv = 1.0f / (e0 + e1);
    float w0 = e0 * inv, w1 = e1 * inv;
    out[(size_t)node * 64 + lane]      = w0 * ge[0][0] + w1 * ge[1][0];
    out[(size_t)node * 64 + lane + 32] = w0 * ge[0][1] + w1 * ge[1][1];
}

extern "C" void kernel_launch(void* const* d_in, const int* in_sizes, int n_in,
                              void* d_out, int out_size) {
    const float* feats0      = (const float*)d_in[0];
    const float* feats1      = (const float*)d_in[1];
    const float* feats2      = (const float*)d_in[2];
    const float* ws_W        = (const float*)d_in[3];
    const float* ws_b        = (const float*)d_in[4];
    const float* adj_vals    = (const float*)d_in[5];
    const float* cell_aff_W  = (const float*)d_in[6];
    const float* cell_aff_b  = (const float*)d_in[7];
    const float* cell_norm_g = (const float*)d_in[8];
    const float* cell_norm_b = (const float*)d_in[9];
    const float* attn1_W     = (const float*)d_in[10];
    const float* attn1_b     = (const float*)d_in[11];
    const float* attn2_W     = (const float*)d_in[12];
    const float* attn2_b     = (const float*)d_in[13];
    // d_in[14] = node_types (contiguous blocks; unused)
    const int* adj_rows      = (const int*)d_in[15];
    const int* adj_cols      = (const int*)d_in[16];
    const int* idxes_seq     = (const int*)d_in[17];   // [2,3]
    const int* idxes_res     = (const int*)d_in[18];   // [2,3]
    float* out = (float*)d_out;

    const int S0_BLOCKS     = (NPT + 63) / 64;
    const int EDGE16_BLOCKS = (NADJ * NNZC / 16 + 255) / 256;
    const int CNT_BLOCKS    = (NADJ * NN + 255) / 256;
    const int GATH4_BLOCKS  = ((NN / 4) * 32 + 255) / 256;   // 4 rows per warp
    const int ZS3_BLOCKS    = (NN * NH * 2 / 4 + 255) / 256;
    const int POST_BLOCKS   = (NN + 7) / 8;

    cudaStream_t s2;
    cudaStreamCreate(&s2);
    cudaEvent_t eFork, eA, eB, eG1, eRes;
    cudaEventCreateWithFlags(&eFork, cudaEventDisableTiming);
    cudaEventCreateWithFlags(&eA, cudaEventDisableTiming);
    cudaEventCreateWithFlags(&eB, cudaEventDisableTiming);
    cudaEventCreateWithFlags(&eG1, cudaEventDisableTiming);
    cudaEventCreateWithFlags(&eRes, cudaEventDisableTiming);
    cudaEventRecord(eFork, 0);
    cudaStreamWaitEvent(s2, eFork, 0);

    // ---- branch B (s2): weights + s0 + zero s3 ----
    wcomb_kernel<<<6, 256, 0, s2>>>(cell_aff_W, cell_aff_b, ws_W, ws_b);
    s0_kernel<<<dim3(S0_BLOCKS, 3), 256, 0, s2>>>(feats0, feats1, feats2);
    zero_s3_kernel<<<ZS3_BLOCKS, 256, 0, s2>>>();
    cudaEventRecord(eB, s2);

    // ---- branch A (default stream): CSR build (atomic-free scatter via ranks) ----
    zero_counts_kernel<<<CNT_BLOCKS, 256>>>();
    hist_kernel<<<EDGE16_BLOCKS, 256>>>(adj_rows);
    scanA_kernel<<<dim3(NT, NADJ), 1024>>>();
    scanB_kernel<<<NADJ, 128>>>();
    scanC_kernel<<<dim3(NT, NADJ), 1024>>>();
    scatter_kernel<<<EDGE16_BLOCKS, 256>>>(adj_rows, adj_cols, adj_vals);
    cudaEventRecord(eA, 0);

    // cross-join: stream0 needs s0+zero(eB); s2 needs CSR(eA)
    cudaStreamWaitEvent(0, eB, 0);
    cudaStreamWaitEvent(s2, eA, 0);

    // ---- stage 1: g1 (s1 = A[seq0] s0)  ||  res1 pass (s3 += A[res1] s0) ----
    spmm_gather_kernel<1><<<dim3(GATH4_BLOCKS, 2), 256>>>(idxes_seq, idxes_res);
    cudaEventRecord(eG1, 0);
    spmm_pass_kernel<<<dim3(GATH4_BLOCKS, 2), 256, 0, s2>>>(idxes_res, 1, 0);

    // ---- stage 2: g2 (s2 = A[seq1] s1 + A[res0] s0)  ||  res2 pass (s3 += A[res2] s1) ----
    spmm_gather_kernel<2><<<dim3(GATH4_BLOCKS, 2), 256>>>(idxes_seq, idxes_res);
    cudaStreamWaitEvent(s2, eG1, 0);
    spmm_pass_kernel<<<dim3(GATH4_BLOCKS, 2), 256, 0, s2>>>(idxes_res, 2, 1);
    cudaEventRecord(eRes, s2);

    // ---- stage 3: s3 += A[seq2] s2, then fused post+mix ----
    spmm_pass_kernel<<<dim3(GATH4_BLOCKS, 2), 256>>>(idxes_seq, 2, 2);
    cudaStreamWaitEvent(0, eRes, 0);
    postmix_kernel<<<POST_BLOCKS, 256>>>(cell_norm_g, cell_norm_b,
                                         attn1_W, attn1_b, attn2_W, attn2_b, out);

    cudaEventDestroy(eFork);
    cudaEventDestroy(eA);
    cudaEventDestroy(eB);
    cudaEventDestroy(eG1);
    cudaEventDestroy(eRes);
    cudaStreamDestroy(s2);
}